// round 12
// baseline (speedup 1.0000x reference)
#include <cuda_runtime.h>
#include <cuda_fp16.h>
#include <math.h>
#include <stdint.h>

#define I_DIM 384
#define J_DIM 384
#define C_DIM 128
#define H_DIM 4
#define ROWS (I_DIM * J_DIM)          // 147456
#define LN_EPS 1e-5f
#define LOG2E 1.4426950408889634f

// ---------------- scratch -------------------------------------------------
__device__ __half g_trih[H_DIM * ROWS];  // [h][q*384+k], pre-scaled by LOG2E
__device__ __half g_qh[ROWS * C_DIM];    // pre-scaled by (1/sqrt(32))*LOG2E
__device__ __half g_kh[ROWS * C_DIM];
__device__ __half g_vh[ROWS * C_DIM];
__device__ __half g_gh[ROWS * C_DIM];
__device__ __half g_oh[ROWS * C_DIM];
__device__ __half g_wh[4][C_DIM * C_DIM];   // wq wk wv wg (fp16)
__device__ __half g_woh[C_DIM * C_DIM];     // wo (fp16)

// ---------------- helpers -------------------------------------------------
__device__ __forceinline__ float ex2(float x) {
    float r; asm("ex2.approx.ftz.f32 %0, %1;" : "=f"(r) : "f"(x)); return r;
}
__device__ __forceinline__ uint32_t pack_h2(float lo, float hi) {
    __half2 h = __float22half2_rn(make_float2(lo, hi));
    return *reinterpret_cast<uint32_t*>(&h);
}
__device__ __forceinline__ uint32_t smaddr(const void* p) {
    return (uint32_t)__cvta_generic_to_shared(p);
}
__device__ __forceinline__ void ldsm4(uint32_t* r, uint32_t addr) {
    asm volatile("ldmatrix.sync.aligned.m8n8.x4.shared.b16 {%0,%1,%2,%3}, [%4];"
        : "=r"(r[0]), "=r"(r[1]), "=r"(r[2]), "=r"(r[3]) : "r"(addr));
}
__device__ __forceinline__ void ldsm4t(uint32_t* r, uint32_t addr) {
    asm volatile("ldmatrix.sync.aligned.m8n8.x4.trans.shared.b16 {%0,%1,%2,%3}, [%4];"
        : "=r"(r[0]), "=r"(r[1]), "=r"(r[2]), "=r"(r[3]) : "r"(addr));
}
__device__ __forceinline__ void mma16(float* c, const uint32_t* a,
                                      uint32_t b0, uint32_t b1) {
    asm volatile(
        "mma.sync.aligned.m16n8k16.row.col.f32.f16.f16.f32 "
        "{%0,%1,%2,%3},{%4,%5,%6,%7},{%8,%9},{%0,%1,%2,%3};"
        : "+f"(c[0]), "+f"(c[1]), "+f"(c[2]), "+f"(c[3])
        : "r"(a[0]), "r"(a[1]), "r"(a[2]), "r"(a[3]), "r"(b0), "r"(b1));
}
__device__ __forceinline__ void cpasync16(uint32_t saddr, const void* g) {
    asm volatile("cp.async.cg.shared.global [%0], [%1], 16;"
                 :: "r"(saddr), "l"(g));
}
__device__ __forceinline__ void cp_commit() {
    asm volatile("cp.async.commit_group;");
}
__device__ __forceinline__ void cp_wait1() {
    asm volatile("cp.async.wait_group 1;");
}
__device__ __forceinline__ void cp_wait0() {
    asm volatile("cp.async.wait_group 0;");
}

#define SAH 136   // fp16 A stride
#define SBH 136   // fp16 B stride
#define SEF 136   // fp32 epilogue stride (out_kernel)

// ---------------- Kernel 0: one-time fp32 -> fp16 weight conversion -------
__global__ __launch_bounds__(256) void cvt_kernel(
    const float* __restrict__ wq, const float* __restrict__ wk,
    const float* __restrict__ wv, const float* __restrict__ wg,
    const float* __restrict__ wo)
{
    int idx = blockIdx.x * 256 + threadIdx.x;      // 0..4095 float4 units
    const float* srcs[5] = {wq, wk, wv, wg, wo};
    __half* dsts[5] = {g_wh[0], g_wh[1], g_wh[2], g_wh[3], g_woh};
    #pragma unroll
    for (int m = 0; m < 5; m++) {
        float4 v = ((const float4*)srcs[m])[idx];
        ((uint2*)dsts[m])[idx] =
            make_uint2(pack_h2(v.x, v.y), pack_h2(v.z, v.w));
    }
}

// ---------------- Kernel 1: fused LN + tri + q/k/v/g projection -----------
// Double-buffered cp.async weight staging overlaps B loads with MMA.
__global__ __launch_bounds__(256, 2) void proj_kernel(
    const float* __restrict__ x,
    const float* __restrict__ ln_g, const float* __restrict__ ln_b,
    const float* __restrict__ w_tri, const float* __restrict__ bg)
{
    extern __shared__ __half shh[];
    __half* As16 = shh;                       // [64][SAH]
    __half* Bbuf0 = As16 + 64 * SAH;          // [128][SBH]
    __half* Bbuf1 = Bbuf0 + 128 * SBH;        // [128][SBH]
    __half* Es    = Bbuf1 + 128 * SBH;        // [64][SBH] epilogue staging

    int m0 = blockIdx.x * 64;
    int tid = threadIdx.x, wid = tid >> 5, lane = tid & 31;
    int warpM = (wid >> 2) * 32, warpN = (wid & 3) * 32;
    int q4 = lane & 3, r8 = lane >> 2;

    // per-thread staging coords (8 x 16B per buffer fill)
    // idx = tid + it*256; kk = idx>>4; c8 = idx&15
    // ---- prologue: async-stage W[0] (overlaps the LN below) ----
    {
        const uint4* Wh = (const uint4*)g_wh[0];
        #pragma unroll
        for (int it = 0; it < 8; it++) {
            int idx = tid + it * 256;
            int kk = idx >> 4, c8 = idx & 15;
            cpasync16(smaddr(Bbuf0 + kk * SBH + c8 * 8), Wh + idx);
        }
        cp_commit();
    }

    // ---- LayerNorm + tri: thread = (row, quarter); coalesced LDG.128 ----
    {
        int row = tid >> 2, qq = tid & 3;
        const float4* xp = (const float4*)(x + ((size_t)(m0 + row)) * 128 + qq * 32);
        float vals[32];
        float sum = 0.0f, ss = 0.0f;
        #pragma unroll
        for (int j4 = 0; j4 < 8; j4++) {
            float4 v = xp[j4];
            vals[4*j4+0] = v.x; vals[4*j4+1] = v.y;
            vals[4*j4+2] = v.z; vals[4*j4+3] = v.w;
            sum += v.x + v.y + v.z + v.w;
            ss  += v.x*v.x + v.y*v.y + v.z*v.z + v.w*v.w;
        }
        sum += __shfl_xor_sync(~0u, sum, 1);
        sum += __shfl_xor_sync(~0u, sum, 2);
        ss  += __shfl_xor_sync(~0u, ss, 1);
        ss  += __shfl_xor_sync(~0u, ss, 2);
        float mean = sum * (1.0f / 128.0f);
        float var  = ss * (1.0f / 128.0f) - mean * mean;
        float rstd = rsqrtf(var + LN_EPS);

        __half* rp16 = As16 + row * SAH + qq * 32;
        const float4* G4 = (const float4*)ln_g + qq * 8;
        const float4* B4 = (const float4*)ln_b + qq * 8;
        const float4* W4 = (const float4*)w_tri + qq * 32;
        float p0 = 0.0f, p1 = 0.0f, p2 = 0.0f, p3 = 0.0f;
        #pragma unroll
        for (int j4 = 0; j4 < 8; j4++) {
            float4 gg = G4[j4], bb = B4[j4];
            float xn0 = (vals[4*j4+0] - mean) * rstd * gg.x + bb.x;
            float xn1 = (vals[4*j4+1] - mean) * rstd * gg.y + bb.y;
            float xn2 = (vals[4*j4+2] - mean) * rstd * gg.z + bb.z;
            float xn3 = (vals[4*j4+3] - mean) * rstd * gg.w + bb.w;
            *(uint32_t*)&rp16[4*j4+0] = pack_h2(xn0, xn1);
            *(uint32_t*)&rp16[4*j4+2] = pack_h2(xn2, xn3);
            float4 w0 = W4[4*j4+0], w1 = W4[4*j4+1];
            float4 w2 = W4[4*j4+2], w3 = W4[4*j4+3];
            p0 += xn0*w0.x + xn1*w1.x + xn2*w2.x + xn3*w3.x;
            p1 += xn0*w0.y + xn1*w1.y + xn2*w2.y + xn3*w3.y;
            p2 += xn0*w0.z + xn1*w1.z + xn2*w2.z + xn3*w3.z;
            p3 += xn0*w0.w + xn1*w1.w + xn2*w2.w + xn3*w3.w;
        }
        #pragma unroll
        for (int o = 1; o <= 2; o <<= 1) {
            p0 += __shfl_xor_sync(~0u, p0, o);
            p1 += __shfl_xor_sync(~0u, p1, o);
            p2 += __shfl_xor_sync(~0u, p2, o);
            p3 += __shfl_xor_sync(~0u, p3, o);
        }
        float pv = (qq == 0) ? p0 : (qq == 1) ? p1 : (qq == 2) ? p2 : p3;
        g_trih[(size_t)qq * ROWS + m0 + row] = __float2half(pv * LOG2E);
    }

    int L = lane;
    uint32_t aAddr = smaddr(As16 + (warpM + (L & 7) + ((L >> 3) & 1) * 8) * SAH
                                 + (L >> 4) * 8);
    uint32_t bOff  = (uint32_t)(((L & 7) + ((L >> 3) & 1) * 8) * SBH
                                 + warpN + (L >> 4) * 8) * 2;
    uint32_t bBase0 = smaddr(Bbuf0) + bOff;
    uint32_t bBase1 = smaddr(Bbuf1) + bOff;

    // ---- 4 weight GEMMs, double-buffered ----
    #pragma unroll 1
    for (int y = 0; y < 4; y++) {
        __half* O = (y == 0) ? g_qh : (y == 1) ? g_kh : (y == 2) ? g_vh : g_gh;

        // 1. prefetch next weight into the other buffer
        if (y < 3) {
            __half* Bn = ((y + 1) & 1) ? Bbuf1 : Bbuf0;
            const uint4* Wh = (const uint4*)g_wh[y + 1];
            #pragma unroll
            for (int it = 0; it < 8; it++) {
                int idx = tid + it * 256;
                int kk = idx >> 4, c8 = idx & 15;
                cpasync16(smaddr(Bn + kk * SBH + c8 * 8), Wh + idx);
            }
            cp_commit();
            cp_wait1();            // current buffer's group complete
        } else {
            cp_wait0();
        }
        __syncthreads();           // staging visible; prev STG(Es) reads done

        uint32_t bAddr = (y & 1) ? bBase1 : bBase0;

        float acc[2][4][4];
        #pragma unroll
        for (int mt = 0; mt < 2; mt++)
            #pragma unroll
            for (int nt = 0; nt < 4; nt++)
                #pragma unroll
                for (int u = 0; u < 4; u++) acc[mt][nt][u] = 0.0f;

        #pragma unroll
        for (int kc = 0; kc < 8; kc++) {
            uint32_t a0[4], a1[4], b0[4], b1[4];
            ldsm4 (a0, aAddr + kc * 32);
            ldsm4 (a1, aAddr + kc * 32 + 16 * SAH * 2);
            ldsm4t(b0, bAddr + kc * 16 * SBH * 2);
            ldsm4t(b1, bAddr + kc * 16 * SBH * 2 + 32);
            mma16(acc[0][0], a0, b0[0], b0[1]);
            mma16(acc[0][1], a0, b0[2], b0[3]);
            mma16(acc[0][2], a0, b1[0], b1[1]);
            mma16(acc[0][3], a0, b1[2], b1[3]);
            mma16(acc[1][0], a1, b0[0], b0[1]);
            mma16(acc[1][1], a1, b0[2], b0[3]);
            mma16(acc[1][2], a1, b1[0], b1[1]);
            mma16(acc[1][3], a1, b1[2], b1[3]);
        }

        // ---- epilogue via smem (Es separate from both B buffers) ----
        const float qscale = 0.17677669529663687f * LOG2E;
        #pragma unroll
        for (int mt = 0; mt < 2; mt++) {
            int r0 = warpM + mt * 16 + r8;
            #pragma unroll
            for (int nt = 0; nt < 4; nt++) {
                int col = warpN + nt * 8 + 2 * q4;
                float v0 = acc[mt][nt][0], v1 = acc[mt][nt][1];
                float v2 = acc[mt][nt][2], v3 = acc[mt][nt][3];
                if (y == 0) { v0 *= qscale; v1 *= qscale; v2 *= qscale; v3 *= qscale; }
                if (y == 3) {
                    float b0v = bg[col], b1v = bg[col + 1];
                    v0 = 1.0f / (1.0f + __expf(-(v0 + b0v)));
                    v1 = 1.0f / (1.0f + __expf(-(v1 + b1v)));
                    v2 = 1.0f / (1.0f + __expf(-(v2 + b0v)));
                    v3 = 1.0f / (1.0f + __expf(-(v3 + b1v)));
                }
                *(uint32_t*)&Es[r0 * SBH + col]       = pack_h2(v0, v1);
                *(uint32_t*)&Es[(r0 + 8) * SBH + col] = pack_h2(v2, v3);
            }
        }
        __syncthreads();
        uint4* O4 = (uint4*)(O + (size_t)m0 * 128);
        #pragma unroll
        for (int it = 0; it < 4; it++) {
            int idx = tid + it * 256;
            int rr = idx >> 4, c8 = idx & 15;
            O4[idx] = *(uint4*)&Es[rr * SBH + c8 * 8];
        }
    }
}

// ---------------- Kernel 2: fp16 MMA flash attention ----------------------
// tri bias software-prefetched one kb-iteration ahead (L2 latency hidden).
#define KVS 40

__global__ __launch_bounds__(768) void attn_kernel(const float* __restrict__ mask)
{
    extern __shared__ float sh[];
    __half* Ksh = (__half*)sh;                 // [384][40]
    __half* Vsh = Ksh + 384 * KVS;             // [384][40]
    float*  mb  = (float*)(Vsh + 384 * KVS);   // [384]

    int i = blockIdx.x, h = blockIdx.y;
    int tid = threadIdx.x, wid = tid >> 5, lane = tid & 31;
    int q4 = lane & 3, r8 = lane >> 2;

    const uint4* K4 = (const uint4*)(g_kh + (size_t)i * J_DIM * 128 + h * 32);
    const uint4* V4 = (const uint4*)(g_vh + (size_t)i * J_DIM * 128 + h * 32);
    #pragma unroll
    for (int it = 0; it < 2; it++) {
        int idx = tid + it * 768;
        int j = idx >> 2, c8 = idx & 3;
        *(uint4*)(Ksh + j * KVS + c8 * 8) = K4[(size_t)j * 16 + c8];
        *(uint4*)(Vsh + j * KVS + c8 * 8) = V4[(size_t)j * 16 + c8];
    }
    if (tid < 384)
        mb[tid] = (LOG2E * 1.0e9f) * (mask[(size_t)i * J_DIM + tid] - 1.0f);
    __syncthreads();

    int qbase = wid * 16;
    uint32_t qa[2][4];
    {
        const __half* Qp = g_qh + ((size_t)i * J_DIM + qbase) * 128 + h * 32;
        #pragma unroll
        for (int dc = 0; dc < 2; dc++) {
            const __half* Qk = Qp + dc * 16;
            qa[dc][0] = *(const uint32_t*)&Qk[r8 * 128 + 2 * q4];
            qa[dc][1] = *(const uint32_t*)&Qk[(r8 + 8) * 128 + 2 * q4];
            qa[dc][2] = *(const uint32_t*)&Qk[r8 * 128 + 2 * q4 + 8];
            qa[dc][3] = *(const uint32_t*)&Qk[(r8 + 8) * 128 + 2 * q4 + 8];
        }
    }

    float oacc[4][4];
    #pragma unroll
    for (int dn = 0; dn < 4; dn++)
        #pragma unroll
        for (int u = 0; u < 4; u++) oacc[dn][u] = 0.0f;
    float lrow0 = 0.0f, lrow1 = 0.0f;

    const __half* triW = g_trih + (size_t)h * ROWS;
    const __half* t0p = triW + (size_t)(qbase + r8) * J_DIM + 2 * q4;
    const __half* t1p = t0p + 8 * J_DIM;
    int L = lane;
    uint32_t kAddr = smaddr(Ksh + (((L >> 4) & 1) * 8 + (L & 7)) * KVS
                                + ((L >> 3) & 1) * 8);
    uint32_t vAddr = smaddr(Vsh + ((L & 7) + ((L >> 3) & 1) * 8) * KVS
                                + (L >> 4) * 8);

    // preload tri for kb=0
    uint32_t tcur[8];
    #pragma unroll
    for (int nt = 0; nt < 4; nt++) {
        tcur[2*nt]   = *(const uint32_t*)(t0p + nt * 8);
        tcur[2*nt+1] = *(const uint32_t*)(t1p + nt * 8);
    }

    #pragma unroll 1
    for (int kb = 0; kb < 12; kb++) {
        int kbase = kb * 32;
        uint32_t kbB = (uint32_t)kbase * (KVS * 2);

        // ---- S = Q K^T ----
        float sacc[4][4];
        #pragma unroll
        for (int nt = 0; nt < 4; nt++)
            #pragma unroll
            for (int u = 0; u < 4; u++) sacc[nt][u] = 0.0f;

        #pragma unroll
        for (int dc = 0; dc < 2; dc++) {
            uint32_t b0[4], b1[4];
            ldsm4(b0, kAddr + kbB + dc * 32);
            ldsm4(b1, kAddr + kbB + 16 * KVS * 2 + dc * 32);
            mma16(sacc[0], qa[dc], b0[0], b0[1]);
            mma16(sacc[1], qa[dc], b0[2], b0[3]);
            mma16(sacc[2], qa[dc], b1[0], b1[1]);
            mma16(sacc[3], qa[dc], b1[2], b1[3]);
        }

        // ---- prefetch tri for kb+1 (consumed next iteration) ----
        uint32_t tnxt[8];
        {
            int nb = (kb < 11) ? (kbase + 32) : kbase;
            #pragma unroll
            for (int nt = 0; nt < 4; nt++) {
                tnxt[2*nt]   = *(const uint32_t*)(t0p + nb + nt * 8);
                tnxt[2*nt+1] = *(const uint32_t*)(t1p + nb + nt * 8);
            }
        }

        // ---- bias + fixed-shift exp2 ----
        #pragma unroll
        for (int nt = 0; nt < 4; nt++) {
            float2 tA = __half22float2(*(const __half2*)&tcur[2*nt]);
            float2 tB = __half22float2(*(const __half2*)&tcur[2*nt+1]);
            float2 mv = *(const float2*)(mb + kbase + nt * 8 + 2 * q4);
            float* s = sacc[nt];
            s[0] = ex2(fminf(s[0] + tA.x + mv.x, 15.0f));
            s[1] = ex2(fminf(s[1] + tA.y + mv.y, 15.0f));
            s[2] = ex2(fminf(s[2] + tB.x + mv.x, 15.0f));
            s[3] = ex2(fminf(s[3] + tB.y + mv.y, 15.0f));
            lrow0 += s[0] + s[1];
            lrow1 += s[2] + s[3];
        }

        // ---- O += P V ----
        #pragma unroll
        for (int kc = 0; kc < 2; kc++) {
            uint32_t pa[4];
            pa[0] = pack_h2(sacc[2*kc][0],   sacc[2*kc][1]);
            pa[1] = pack_h2(sacc[2*kc][2],   sacc[2*kc][3]);
            pa[2] = pack_h2(sacc[2*kc+1][0], sacc[2*kc+1][1]);
            pa[3] = pack_h2(sacc[2*kc+1][2], sacc[2*kc+1][3]);

            uint32_t vb0[4], vb1[4];
            uint32_t vOff = kbB + (uint32_t)kc * 16 * KVS * 2;
            ldsm4t(vb0, vAddr + vOff);
            ldsm4t(vb1, vAddr + vOff + 32);
            mma16(oacc[0], pa, vb0[0], vb0[1]);
            mma16(oacc[1], pa, vb0[2], vb0[3]);
            mma16(oacc[2], pa, vb1[0], vb1[1]);
            mma16(oacc[3], pa, vb1[2], vb1[3]);
        }

        #pragma unroll
        for (int u = 0; u < 8; u++) tcur[u] = tnxt[u];
    }

    lrow0 += __shfl_xor_sync(~0u, lrow0, 1);
    lrow0 += __shfl_xor_sync(~0u, lrow0, 2);
    lrow1 += __shfl_xor_sync(~0u, lrow1, 1);
    lrow1 += __shfl_xor_sync(~0u, lrow1, 2);

    {
        float inv0 = 1.0f / fmaxf(lrow0, 1e-30f);
        float inv1 = 1.0f / fmaxf(lrow1, 1e-30f);
        size_t row0 = ((size_t)i * J_DIM + qbase + r8) * 128 + h * 32;
        size_t row1 = row0 + (size_t)8 * 128;
        #pragma unroll
        for (int dn = 0; dn < 4; dn++) {
            int c = dn * 8 + 2 * q4;
            float2 gv0 = __half22float2(*(const __half2*)&g_gh[row0 + c]);
            float2 gv1 = __half22float2(*(const __half2*)&g_gh[row1 + c]);
            *(uint32_t*)&g_oh[row0 + c] =
                pack_h2(oacc[dn][0] * inv0 * gv0.x, oacc[dn][1] * inv0 * gv0.y);
            *(uint32_t*)&g_oh[row1 + c] =
                pack_h2(oacc[dn][2] * inv1 * gv1.x, oacc[dn][3] * inv1 * gv1.y);
        }
    }
}

// ---------------- Kernel 3: output projection (fp16 MMA) ------------------
__global__ __launch_bounds__(256, 3) void out_kernel(
    const float* __restrict__ bo, float* __restrict__ out)
{
    extern __shared__ __half shh[];
    __half* As16 = shh;                  // [64][SAH]
    __half* Bs16 = As16 + 64 * SAH;      // [128][SBH]; reused as fp32 epilogue

    int m0 = blockIdx.x * 64;
    int tid = threadIdx.x, wid = tid >> 5, lane = tid & 31;
    int warpM = (wid >> 2) * 32, warpN = (wid & 3) * 32;
    int q4 = lane & 3, r8 = lane >> 2;

    const uint4* A4 = (const uint4*)(g_oh + (size_t)m0 * 128);
    #pragma unroll
    for (int it = 0; it < 4; it++) {
        int idx = tid + it * 256;
        int rr = idx >> 4, c8 = idx & 15;
        *(uint4*)(As16 + rr * SAH + c8 * 8) = A4[idx];
    }
    const uint4* Wh = (const uint4*)g_woh;
    #pragma unroll
    for (int it = 0; it < 8; it++) {
        int idx = tid + it * 256;
        int kk = idx >> 4, c8 = idx & 15;
        *(uint4*)&Bs16[kk * SBH + c8 * 8] = Wh[idx];
    }
    __syncthreads();

    int L = lane;
    uint32_t aAddr = smaddr(As16 + (warpM + (L & 7) + ((L >> 3) & 1) * 8) * SAH
                                 + (L >> 4) * 8);
    uint32_t bAddr = smaddr(Bs16 + ((L & 7) + ((L >> 3) & 1) * 8) * SBH
                                 + warpN + (L >> 4) * 8);

    float acc[2][4][4];
    #pragma unroll
    for (int mt = 0; mt < 2; mt++)
        #pragma unroll
        for (int nt = 0; nt < 4; nt++)
            #pragma unroll
            for (int u = 0; u < 4; u++) acc[mt][nt][u] = 0.0f;

    #pragma unroll
    for (int kc = 0; kc < 8; kc++) {
        uint32_t a0[4], a1[4], b0[4], b1[4];
        ldsm4 (a0, aAddr + kc * 32);
        ldsm4 (a1, aAddr + kc * 32 + 16 * SAH * 2);
        ldsm4t(b0, bAddr + kc * 16 * SBH * 2);
        ldsm4t(b1, bAddr + kc * 16 * SBH * 2 + 32);
        mma16(acc[0][0], a0, b0[0], b0[1]);
        mma16(acc[0][1], a0, b0[2], b0[3]);
        mma16(acc[0][2], a0, b1[0], b1[1]);
        mma16(acc[0][3], a0, b1[2], b1[3]);
        mma16(acc[1][0], a1, b0[0], b0[1]);
        mma16(acc[1][1], a1, b0[2], b0[3]);
        mma16(acc[1][2], a1, b1[0], b1[1]);
        mma16(acc[1][3], a1, b1[2], b1[3]);
    }

    __syncthreads();
    float* Es32 = (float*)Bs16;          // [64][SEF] fp32
    #pragma unroll
    for (int mt = 0; mt < 2; mt++) {
        int r0 = warpM + mt * 16 + r8;
        #pragma unroll
        for (int nt = 0; nt < 4; nt++) {
            int col = warpN + nt * 8 + 2 * q4;
            float b0v = bo[col], b1v = bo[col + 1];
            *(float2*)&Es32[r0 * SEF + col] =
                make_float2(acc[mt][nt][0] + b0v, acc[mt][nt][1] + b1v);
            *(float2*)&Es32[(r0 + 8) * SEF + col] =
                make_float2(acc[mt][nt][2] + b0v, acc[mt][nt][3] + b1v);
        }
    }
    __syncthreads();
    float4* O4 = (float4*)(out + (size_t)m0 * 128);
    #pragma unroll
    for (int it = 0; it < 8; it++) {
        int idx = tid + it * 256;
        int rr = idx >> 5, c4 = idx & 31;
        O4[idx] = *(float4*)&Es32[rr * SEF + c4 * 4];
    }
}

// ---------------- launch ---------------------------------------------------
extern "C" void kernel_launch(void* const* d_in, const int* in_sizes, int n_in,
                              void* d_out, int out_size)
{
    const float* x     = (const float*)d_in[0];
    const float* mask  = (const float*)d_in[1];
    const float* ln_g  = (const float*)d_in[2];
    const float* ln_b  = (const float*)d_in[3];
    const float* w_tri = (const float*)d_in[4];
    const float* wq    = (const float*)d_in[5];
    const float* wk    = (const float*)d_in[6];
    const float* wv    = (const float*)d_in[7];
    const float* wg    = (const float*)d_in[8];
    const float* bg    = (const float*)d_in[9];
    const float* wo    = (const float*)d_in[10];
    const float* bo    = (const float*)d_in[11];
    float* out = (float*)d_out;

    const int SMEM_PROJ = (64 * SAH + 2 * 128 * SBH + 64 * SBH) * 2;  // 104448
    const int SMEM_OUT  = 64 * SAH * 2 + 128 * SBH * 2;               // 52224
    const int SMEM_ATTN = 2 * 384 * KVS * 2 + 384 * 4;                // 62976
    cudaFuncSetAttribute(proj_kernel,
                         cudaFuncAttributeMaxDynamicSharedMemorySize, SMEM_PROJ);
    cudaFuncSetAttribute(out_kernel,
                         cudaFuncAttributeMaxDynamicSharedMemorySize, SMEM_OUT);
    cudaFuncSetAttribute(attn_kernel,
                         cudaFuncAttributeMaxDynamicSharedMemorySize, SMEM_ATTN);

    cvt_kernel<<<16, 256>>>(wq, wk, wv, wg, wo);
    proj_kernel<<<ROWS / 64, 256, SMEM_PROJ>>>(x, ln_g, ln_b, w_tri, bg);
    attn_kernel<<<dim3(I_DIM, H_DIM), 768, SMEM_ATTN>>>(mask);
    out_kernel<<<ROWS / 64, 256, SMEM_OUT>>>(bo, out);
}

// round 13
// speedup vs baseline: 1.0245x; 1.0245x over previous
#include <cuda_runtime.h>
#include <cuda_fp16.h>
#include <math.h>
#include <stdint.h>

#define I_DIM 384
#define J_DIM 384
#define C_DIM 128
#define H_DIM 4
#define ROWS (I_DIM * J_DIM)          // 147456
#define LN_EPS 1e-5f
#define LOG2E 1.4426950408889634f

// ---------------- scratch -------------------------------------------------
__device__ __half g_trih[H_DIM * ROWS];  // [h][q*384+k], pre-scaled by LOG2E
__device__ __half g_qh[ROWS * C_DIM];    // pre-scaled by (1/sqrt(32))*LOG2E
__device__ __half g_kh[ROWS * C_DIM];
__device__ __half g_vh[ROWS * C_DIM];
__device__ __half g_gh[ROWS * C_DIM];
__device__ __half g_oh[ROWS * C_DIM];
__device__ __half g_wh[4][C_DIM * C_DIM];   // wq wk wv wg (fp16)
__device__ __half g_woh[C_DIM * C_DIM];     // wo (fp16)

// ---------------- helpers -------------------------------------------------
__device__ __forceinline__ float ex2(float x) {
    float r; asm("ex2.approx.ftz.f32 %0, %1;" : "=f"(r) : "f"(x)); return r;
}
__device__ __forceinline__ uint32_t pack_h2(float lo, float hi) {
    __half2 h = __float22half2_rn(make_float2(lo, hi));
    return *reinterpret_cast<uint32_t*>(&h);
}
__device__ __forceinline__ uint32_t smaddr(const void* p) {
    return (uint32_t)__cvta_generic_to_shared(p);
}
__device__ __forceinline__ void ldsm4(uint32_t* r, uint32_t addr) {
    asm volatile("ldmatrix.sync.aligned.m8n8.x4.shared.b16 {%0,%1,%2,%3}, [%4];"
        : "=r"(r[0]), "=r"(r[1]), "=r"(r[2]), "=r"(r[3]) : "r"(addr));
}
__device__ __forceinline__ void ldsm4t(uint32_t* r, uint32_t addr) {
    asm volatile("ldmatrix.sync.aligned.m8n8.x4.trans.shared.b16 {%0,%1,%2,%3}, [%4];"
        : "=r"(r[0]), "=r"(r[1]), "=r"(r[2]), "=r"(r[3]) : "r"(addr));
}
__device__ __forceinline__ void mma16(float* c, const uint32_t* a,
                                      uint32_t b0, uint32_t b1) {
    asm volatile(
        "mma.sync.aligned.m16n8k16.row.col.f32.f16.f16.f32 "
        "{%0,%1,%2,%3},{%4,%5,%6,%7},{%8,%9},{%0,%1,%2,%3};"
        : "+f"(c[0]), "+f"(c[1]), "+f"(c[2]), "+f"(c[3])
        : "r"(a[0]), "r"(a[1]), "r"(a[2]), "r"(a[3]), "r"(b0), "r"(b1));
}

#define SAH 136   // fp16 A stride
#define SBH 136   // fp16 B stride
#define SEF 136   // fp32 epilogue stride (out_kernel)

// ---------------- Kernel 0: one-time fp32 -> fp16 weight conversion -------
__global__ __launch_bounds__(256) void cvt_kernel(
    const float* __restrict__ wq, const float* __restrict__ wk,
    const float* __restrict__ wv, const float* __restrict__ wg,
    const float* __restrict__ wo)
{
    int idx = blockIdx.x * 256 + threadIdx.x;      // 0..4095 float4 units
    const float* srcs[5] = {wq, wk, wv, wg, wo};
    __half* dsts[5] = {g_wh[0], g_wh[1], g_wh[2], g_wh[3], g_woh};
    #pragma unroll
    for (int m = 0; m < 5; m++) {
        float4 v = ((const float4*)srcs[m])[idx];
        ((uint2*)dsts[m])[idx] =
            make_uint2(pack_h2(v.x, v.y), pack_h2(v.z, v.w));
    }
}

// ---------------- Kernel 1: fused LN + tri + q/k/v/g projection -----------
// A-fragments hoisted to registers once; the 4 weight GEMMs only touch B
// in smem. As16 doubles as the epilogue staging buffer after the hoist.
__global__ __launch_bounds__(256, 2) void proj_kernel(
    const float* __restrict__ x,
    const float* __restrict__ ln_g, const float* __restrict__ ln_b,
    const float* __restrict__ w_tri, const float* __restrict__ bg)
{
    extern __shared__ __half shh[];
    __half* As16 = shh;                  // [64][SAH]; reused as epilogue tile
    __half* Bs16 = As16 + 64 * SAH;      // [128][SBH]

    int m0 = blockIdx.x * 64;
    int tid = threadIdx.x, wid = tid >> 5, lane = tid & 31;
    int warpM = (wid >> 2) * 32, warpN = (wid & 3) * 32;
    int q4 = lane & 3, r8 = lane >> 2;

    // ---- LayerNorm + tri: thread = (row, quarter); coalesced LDG.128 ----
    {
        int row = tid >> 2, qq = tid & 3;
        const float4* xp = (const float4*)(x + ((size_t)(m0 + row)) * 128 + qq * 32);
        float vals[32];
        float sum = 0.0f, ss = 0.0f;
        #pragma unroll
        for (int j4 = 0; j4 < 8; j4++) {
            float4 v = xp[j4];
            vals[4*j4+0] = v.x; vals[4*j4+1] = v.y;
            vals[4*j4+2] = v.z; vals[4*j4+3] = v.w;
            sum += v.x + v.y + v.z + v.w;
            ss  += v.x*v.x + v.y*v.y + v.z*v.z + v.w*v.w;
        }
        sum += __shfl_xor_sync(~0u, sum, 1);
        sum += __shfl_xor_sync(~0u, sum, 2);
        ss  += __shfl_xor_sync(~0u, ss, 1);
        ss  += __shfl_xor_sync(~0u, ss, 2);
        float mean = sum * (1.0f / 128.0f);
        float var  = ss * (1.0f / 128.0f) - mean * mean;
        float rstd = rsqrtf(var + LN_EPS);

        __half* rp16 = As16 + row * SAH + qq * 32;
        const float4* G4 = (const float4*)ln_g + qq * 8;
        const float4* B4 = (const float4*)ln_b + qq * 8;
        const float4* W4 = (const float4*)w_tri + qq * 32;
        float p0 = 0.0f, p1 = 0.0f, p2 = 0.0f, p3 = 0.0f;
        #pragma unroll
        for (int j4 = 0; j4 < 8; j4++) {
            float4 gg = G4[j4], bb = B4[j4];
            float xn0 = (vals[4*j4+0] - mean) * rstd * gg.x + bb.x;
            float xn1 = (vals[4*j4+1] - mean) * rstd * gg.y + bb.y;
            float xn2 = (vals[4*j4+2] - mean) * rstd * gg.z + bb.z;
            float xn3 = (vals[4*j4+3] - mean) * rstd * gg.w + bb.w;
            *(uint32_t*)&rp16[4*j4+0] = pack_h2(xn0, xn1);
            *(uint32_t*)&rp16[4*j4+2] = pack_h2(xn2, xn3);
            float4 w0 = W4[4*j4+0], w1 = W4[4*j4+1];
            float4 w2 = W4[4*j4+2], w3 = W4[4*j4+3];
            p0 += xn0*w0.x + xn1*w1.x + xn2*w2.x + xn3*w3.x;
            p1 += xn0*w0.y + xn1*w1.y + xn2*w2.y + xn3*w3.y;
            p2 += xn0*w0.z + xn1*w1.z + xn2*w2.z + xn3*w3.z;
            p3 += xn0*w0.w + xn1*w1.w + xn2*w2.w + xn3*w3.w;
        }
        #pragma unroll
        for (int o = 1; o <= 2; o <<= 1) {
            p0 += __shfl_xor_sync(~0u, p0, o);
            p1 += __shfl_xor_sync(~0u, p1, o);
            p2 += __shfl_xor_sync(~0u, p2, o);
            p3 += __shfl_xor_sync(~0u, p3, o);
        }
        float pv = (qq == 0) ? p0 : (qq == 1) ? p1 : (qq == 2) ? p2 : p3;
        g_trih[(size_t)qq * ROWS + m0 + row] = __float2half(pv * LOG2E);
    }
    __syncthreads();                     // A tile complete in smem

    int L = lane;
    uint32_t aAddr = smaddr(As16 + (warpM + (L & 7) + ((L >> 3) & 1) * 8) * SAH
                                 + (L >> 4) * 8);
    uint32_t bAddr = smaddr(Bs16 + ((L & 7) + ((L >> 3) & 1) * 8) * SBH
                                 + warpN + (L >> 4) * 8);

    // ---- hoist all A fragments to registers (invariant across y) ----
    uint32_t afr[2][8][4];
    #pragma unroll
    for (int kc = 0; kc < 8; kc++) {
        ldsm4(afr[0][kc], aAddr + kc * 32);
        ldsm4(afr[1][kc], aAddr + kc * 32 + 16 * SAH * 2);
    }

    // ---- 4 weight GEMMs; only B staged per iteration ----
    #pragma unroll 1
    for (int y = 0; y < 4; y++) {
        __half* O = (y == 0) ? g_qh : (y == 1) ? g_kh : (y == 2) ? g_vh : g_gh;

        // stage B. Prior y's B ldsm + Es traffic are fenced by the epilogue
        // sync at the end of the previous iteration; first y is fenced by
        // the post-LN sync (all warps past their A-frag LDSMs).
        const uint4* Wh = (const uint4*)g_wh[y];
        #pragma unroll
        for (int it = 0; it < 8; it++) {
            int idx = tid + it * 256;
            int kk = idx >> 4, c8 = idx & 15;
            *(uint4*)&Bs16[kk * SBH + c8 * 8] = Wh[idx];
        }
        __syncthreads();

        float acc[2][4][4];
        #pragma unroll
        for (int mt = 0; mt < 2; mt++)
            #pragma unroll
            for (int nt = 0; nt < 4; nt++)
                #pragma unroll
                for (int u = 0; u < 4; u++) acc[mt][nt][u] = 0.0f;

        #pragma unroll
        for (int kc = 0; kc < 8; kc++) {
            uint32_t b0[4], b1[4];
            ldsm4t(b0, bAddr + kc * 16 * SBH * 2);
            ldsm4t(b1, bAddr + kc * 16 * SBH * 2 + 32);
            mma16(acc[0][0], afr[0][kc], b0[0], b0[1]);
            mma16(acc[0][1], afr[0][kc], b0[2], b0[3]);
            mma16(acc[0][2], afr[0][kc], b1[0], b1[1]);
            mma16(acc[0][3], afr[0][kc], b1[2], b1[3]);
            mma16(acc[1][0], afr[1][kc], b0[0], b0[1]);
            mma16(acc[1][1], afr[1][kc], b0[2], b0[3]);
            mma16(acc[1][2], afr[1][kc], b1[0], b1[1]);
            mma16(acc[1][3], afr[1][kc], b1[2], b1[3]);
        }

        // ---- epilogue via smem (Es = As16, free after A-frag hoist) ----
        __syncthreads();                 // all B ldsm done; prev Es STGs done
        __half* Es = As16;
        const float qscale = 0.17677669529663687f * LOG2E;
        #pragma unroll
        for (int mt = 0; mt < 2; mt++) {
            int r0 = warpM + mt * 16 + r8;
            #pragma unroll
            for (int nt = 0; nt < 4; nt++) {
                int col = warpN + nt * 8 + 2 * q4;
                float v0 = acc[mt][nt][0], v1 = acc[mt][nt][1];
                float v2 = acc[mt][nt][2], v3 = acc[mt][nt][3];
                if (y == 0) { v0 *= qscale; v1 *= qscale; v2 *= qscale; v3 *= qscale; }
                if (y == 3) {
                    float b0v = bg[col], b1v = bg[col + 1];
                    v0 = 1.0f / (1.0f + __expf(-(v0 + b0v)));
                    v1 = 1.0f / (1.0f + __expf(-(v1 + b1v)));
                    v2 = 1.0f / (1.0f + __expf(-(v2 + b0v)));
                    v3 = 1.0f / (1.0f + __expf(-(v3 + b1v)));
                }
                *(uint32_t*)&Es[r0 * SAH + col]       = pack_h2(v0, v1);
                *(uint32_t*)&Es[(r0 + 8) * SAH + col] = pack_h2(v2, v3);
            }
        }
        __syncthreads();
        uint4* O4 = (uint4*)(O + (size_t)m0 * 128);
        #pragma unroll
        for (int it = 0; it < 4; it++) {
            int idx = tid + it * 256;
            int rr = idx >> 4, c8 = idx & 15;
            O4[idx] = *(uint4*)&Es[rr * SAH + c8 * 8];
        }
        __syncthreads();                 // Es reads done before next y reuse
    }
}

// ---------------- Kernel 2: fp16 MMA flash attention (R11 form) -----------
#define KVS 40

__global__ __launch_bounds__(768) void attn_kernel(const float* __restrict__ mask)
{
    extern __shared__ float sh[];
    __half* Ksh = (__half*)sh;                 // [384][40]
    __half* Vsh = Ksh + 384 * KVS;             // [384][40]
    float*  mb  = (float*)(Vsh + 384 * KVS);   // [384]

    int i = blockIdx.x, h = blockIdx.y;
    int tid = threadIdx.x, wid = tid >> 5, lane = tid & 31;
    int q4 = lane & 3, r8 = lane >> 2;

    const uint4* K4 = (const uint4*)(g_kh + (size_t)i * J_DIM * 128 + h * 32);
    const uint4* V4 = (const uint4*)(g_vh + (size_t)i * J_DIM * 128 + h * 32);
    #pragma unroll
    for (int it = 0; it < 2; it++) {
        int idx = tid + it * 768;
        int j = idx >> 2, c8 = idx & 3;
        *(uint4*)(Ksh + j * KVS + c8 * 8) = K4[(size_t)j * 16 + c8];
        *(uint4*)(Vsh + j * KVS + c8 * 8) = V4[(size_t)j * 16 + c8];
    }
    if (tid < 384)
        mb[tid] = (LOG2E * 1.0e9f) * (mask[(size_t)i * J_DIM + tid] - 1.0f);
    __syncthreads();

    int qbase = wid * 16;
    uint32_t qa[2][4];
    {
        const __half* Qp = g_qh + ((size_t)i * J_DIM + qbase) * 128 + h * 32;
        #pragma unroll
        for (int dc = 0; dc < 2; dc++) {
            const __half* Qk = Qp + dc * 16;
            qa[dc][0] = *(const uint32_t*)&Qk[r8 * 128 + 2 * q4];
            qa[dc][1] = *(const uint32_t*)&Qk[(r8 + 8) * 128 + 2 * q4];
            qa[dc][2] = *(const uint32_t*)&Qk[r8 * 128 + 2 * q4 + 8];
            qa[dc][3] = *(const uint32_t*)&Qk[(r8 + 8) * 128 + 2 * q4 + 8];
        }
    }

    float oacc[4][4];
    #pragma unroll
    for (int dn = 0; dn < 4; dn++)
        #pragma unroll
        for (int u = 0; u < 4; u++) oacc[dn][u] = 0.0f;
    float lrow0 = 0.0f, lrow1 = 0.0f;

    const __half* triW = g_trih + (size_t)h * ROWS;
    int L = lane;
    uint32_t kAddr = smaddr(Ksh + (((L >> 4) & 1) * 8 + (L & 7)) * KVS
                                + ((L >> 3) & 1) * 8);
    uint32_t vAddr = smaddr(Vsh + ((L & 7) + ((L >> 3) & 1) * 8) * KVS
                                + (L >> 4) * 8);

    #pragma unroll 1
    for (int kb = 0; kb < 12; kb++) {
        int kbase = kb * 32;
        uint32_t kbB = (uint32_t)kbase * (KVS * 2);

        float sacc[4][4];
        #pragma unroll
        for (int nt = 0; nt < 4; nt++)
            #pragma unroll
            for (int u = 0; u < 4; u++) sacc[nt][u] = 0.0f;

        #pragma unroll
        for (int dc = 0; dc < 2; dc++) {
            uint32_t b0[4], b1[4];
            ldsm4(b0, kAddr + kbB + dc * 32);
            ldsm4(b1, kAddr + kbB + 16 * KVS * 2 + dc * 32);
            mma16(sacc[0], qa[dc], b0[0], b0[1]);
            mma16(sacc[1], qa[dc], b0[2], b0[3]);
            mma16(sacc[2], qa[dc], b1[0], b1[1]);
            mma16(sacc[3], qa[dc], b1[2], b1[3]);
        }

        {
            int qrow = qbase + r8;
            const __half* t0p = triW + (size_t)qrow * J_DIM + kbase + 2 * q4;
            const __half* t1p = t0p + 8 * J_DIM;
            #pragma unroll
            for (int nt = 0; nt < 4; nt++) {
                float2 tA = __half22float2(*(const __half2*)(t0p + nt * 8));
                float2 tB = __half22float2(*(const __half2*)(t1p + nt * 8));
                float2 mv = *(const float2*)(mb + kbase + nt * 8 + 2 * q4);
                float* s = sacc[nt];
                s[0] = ex2(fminf(s[0] + tA.x + mv.x, 15.0f));
                s[1] = ex2(fminf(s[1] + tA.y + mv.y, 15.0f));
                s[2] = ex2(fminf(s[2] + tB.x + mv.x, 15.0f));
                s[3] = ex2(fminf(s[3] + tB.y + mv.y, 15.0f));
                lrow0 += s[0] + s[1];
                lrow1 += s[2] + s[3];
            }
        }

        #pragma unroll
        for (int kc = 0; kc < 2; kc++) {
            uint32_t pa[4];
            pa[0] = pack_h2(sacc[2*kc][0],   sacc[2*kc][1]);
            pa[1] = pack_h2(sacc[2*kc][2],   sacc[2*kc][3]);
            pa[2] = pack_h2(sacc[2*kc+1][0], sacc[2*kc+1][1]);
            pa[3] = pack_h2(sacc[2*kc+1][2], sacc[2*kc+1][3]);

            uint32_t vb0[4], vb1[4];
            uint32_t vOff = kbB + (uint32_t)kc * 16 * KVS * 2;
            ldsm4t(vb0, vAddr + vOff);
            ldsm4t(vb1, vAddr + vOff + 32);
            mma16(oacc[0], pa, vb0[0], vb0[1]);
            mma16(oacc[1], pa, vb0[2], vb0[3]);
            mma16(oacc[2], pa, vb1[0], vb1[1]);
            mma16(oacc[3], pa, vb1[2], vb1[3]);
        }
    }

    lrow0 += __shfl_xor_sync(~0u, lrow0, 1);
    lrow0 += __shfl_xor_sync(~0u, lrow0, 2);
    lrow1 += __shfl_xor_sync(~0u, lrow1, 1);
    lrow1 += __shfl_xor_sync(~0u, lrow1, 2);

    {
        float inv0 = 1.0f / fmaxf(lrow0, 1e-30f);
        float inv1 = 1.0f / fmaxf(lrow1, 1e-30f);
        size_t row0 = ((size_t)i * J_DIM + qbase + r8) * 128 + h * 32;
        size_t row1 = row0 + (size_t)8 * 128;
        #pragma unroll
        for (int dn = 0; dn < 4; dn++) {
            int c = dn * 8 + 2 * q4;
            float2 gv0 = __half22float2(*(const __half2*)&g_gh[row0 + c]);
            float2 gv1 = __half22float2(*(const __half2*)&g_gh[row1 + c]);
            *(uint32_t*)&g_oh[row0 + c] =
                pack_h2(oacc[dn][0] * inv0 * gv0.x, oacc[dn][1] * inv0 * gv0.y);
            *(uint32_t*)&g_oh[row1 + c] =
                pack_h2(oacc[dn][2] * inv1 * gv1.x, oacc[dn][3] * inv1 * gv1.y);
        }
    }
}

// ---------------- Kernel 3: output projection (fp16 MMA) ------------------
__global__ __launch_bounds__(256, 3) void out_kernel(
    const float* __restrict__ bo, float* __restrict__ out)
{
    extern __shared__ __half shh[];
    __half* As16 = shh;                  // [64][SAH]
    __half* Bs16 = As16 + 64 * SAH;      // [128][SBH]; reused as fp32 epilogue

    int m0 = blockIdx.x * 64;
    int tid = threadIdx.x, wid = tid >> 5, lane = tid & 31;
    int warpM = (wid >> 2) * 32, warpN = (wid & 3) * 32;
    int q4 = lane & 3, r8 = lane >> 2;

    const uint4* A4 = (const uint4*)(g_oh + (size_t)m0 * 128);
    #pragma unroll
    for (int it = 0; it < 4; it++) {
        int idx = tid + it * 256;
        int rr = idx >> 4, c8 = idx & 15;
        *(uint4*)(As16 + rr * SAH + c8 * 8) = A4[idx];
    }
    const uint4* Wh = (const uint4*)g_woh;
    #pragma unroll
    for (int it = 0; it < 8; it++) {
        int idx = tid + it * 256;
        int kk = idx >> 4, c8 = idx & 15;
        *(uint4*)&Bs16[kk * SBH + c8 * 8] = Wh[idx];
    }
    __syncthreads();

    int L = lane;
    uint32_t aAddr = smaddr(As16 + (warpM + (L & 7) + ((L >> 3) & 1) * 8) * SAH
                                 + (L >> 4) * 8);
    uint32_t bAddr = smaddr(Bs16 + ((L & 7) + ((L >> 3) & 1) * 8) * SBH
                                 + warpN + (L >> 4) * 8);

    float acc[2][4][4];
    #pragma unroll
    for (int mt = 0; mt < 2; mt++)
        #pragma unroll
        for (int nt = 0; nt < 4; nt++)
            #pragma unroll
            for (int u = 0; u < 4; u++) acc[mt][nt][u] = 0.0f;

    #pragma unroll
    for (int kc = 0; kc < 8; kc++) {
        uint32_t a0[4], a1[4], b0[4], b1[4];
        ldsm4 (a0, aAddr + kc * 32);
        ldsm4 (a1, aAddr + kc * 32 + 16 * SAH * 2);
        ldsm4t(b0, bAddr + kc * 16 * SBH * 2);
        ldsm4t(b1, bAddr + kc * 16 * SBH * 2 + 32);
        mma16(acc[0][0], a0, b0[0], b0[1]);
        mma16(acc[0][1], a0, b0[2], b0[3]);
        mma16(acc[0][2], a0, b1[0], b1[1]);
        mma16(acc[0][3], a0, b1[2], b1[3]);
        mma16(acc[1][0], a1, b0[0], b0[1]);
        mma16(acc[1][1], a1, b0[2], b0[3]);
        mma16(acc[1][2], a1, b1[0], b1[1]);
        mma16(acc[1][3], a1, b1[2], b1[3]);
    }

    __syncthreads();
    float* Es32 = (float*)Bs16;          // [64][SEF] fp32
    #pragma unroll
    for (int mt = 0; mt < 2; mt++) {
        int r0 = warpM + mt * 16 + r8;
        #pragma unroll
        for (int nt = 0; nt < 4; nt++) {
            int col = warpN + nt * 8 + 2 * q4;
            float b0v = bo[col], b1v = bo[col + 1];
            *(float2*)&Es32[r0 * SEF + col] =
                make_float2(acc[mt][nt][0] + b0v, acc[mt][nt][1] + b1v);
            *(float2*)&Es32[(r0 + 8) * SEF + col] =
                make_float2(acc[mt][nt][2] + b0v, acc[mt][nt][3] + b1v);
        }
    }
    __syncthreads();
    float4* O4 = (float4*)(out + (size_t)m0 * 128);
    #pragma unroll
    for (int it = 0; it < 8; it++) {
        int idx = tid + it * 256;
        int rr = idx >> 5, c4 = idx & 31;
        O4[idx] = *(float4*)&Es32[rr * SEF + c4 * 4];
    }
}

// ---------------- launch ---------------------------------------------------
extern "C" void kernel_launch(void* const* d_in, const int* in_sizes, int n_in,
                              void* d_out, int out_size)
{
    const float* x     = (const float*)d_in[0];
    const float* mask  = (const float*)d_in[1];
    const float* ln_g  = (const float*)d_in[2];
    const float* ln_b  = (const float*)d_in[3];
    const float* w_tri = (const float*)d_in[4];
    const float* wq    = (const float*)d_in[5];
    const float* wk    = (const float*)d_in[6];
    const float* wv    = (const float*)d_in[7];
    const float* wg    = (const float*)d_in[8];
    const float* bg    = (const float*)d_in[9];
    const float* wo    = (const float*)d_in[10];
    const float* bo    = (const float*)d_in[11];
    float* out = (float*)d_out;

    const int SMEM_GEMM = 64 * SAH * 2 + 128 * SBH * 2;     // 52224
    const int SMEM_ATTN = 2 * 384 * KVS * 2 + 384 * 4;      // 62976
    cudaFuncSetAttribute(proj_kernel,
                         cudaFuncAttributeMaxDynamicSharedMemorySize, SMEM_GEMM);
    cudaFuncSetAttribute(out_kernel,
                         cudaFuncAttributeMaxDynamicSharedMemorySize, SMEM_GEMM);
    cudaFuncSetAttribute(attn_kernel,
                         cudaFuncAttributeMaxDynamicSharedMemorySize, SMEM_ATTN);

    cvt_kernel<<<16, 256>>>(wq, wk, wv, wg, wo);
    proj_kernel<<<ROWS / 64, 256, SMEM_GEMM>>>(x, ln_g, ln_b, w_tri, bg);
    attn_kernel<<<dim3(I_DIM, H_DIM), 768, SMEM_ATTN>>>(mask);
    out_kernel<<<ROWS / 64, 256, SMEM_GEMM>>>(bo, out);
}

// round 14
// speedup vs baseline: 1.0276x; 1.0030x over previous
#include <cuda_runtime.h>
#include <cuda_fp16.h>
#include <math.h>
#include <stdint.h>

#define I_DIM 384
#define J_DIM 384
#define C_DIM 128
#define H_DIM 4
#define ROWS (I_DIM * J_DIM)          // 147456
#define LN_EPS 1e-5f
#define LOG2E 1.4426950408889634f

// ---------------- scratch -------------------------------------------------
__device__ __half g_trih[H_DIM * ROWS];  // [h][q*384+k], pre-scaled by LOG2E
__device__ __half g_qh[ROWS * C_DIM];    // pre-scaled by (1/sqrt(32))*LOG2E
__device__ __half g_kh[ROWS * C_DIM];
__device__ __half g_vh[ROWS * C_DIM];
__device__ __half g_gh[ROWS * C_DIM];
__device__ __half g_oh[ROWS * C_DIM];
__device__ __half g_wh[4][C_DIM * C_DIM];   // wq wk wv wg (fp16)
__device__ __half g_woh[C_DIM * C_DIM];     // wo (fp16)

// ---------------- helpers -------------------------------------------------
__device__ __forceinline__ uint32_t pack_h2(float lo, float hi) {
    __half2 h = __float22half2_rn(make_float2(lo, hi));
    return *reinterpret_cast<uint32_t*>(&h);
}
__device__ __forceinline__ uint32_t ex2h2(uint32_t x) {
    uint32_t r; asm("ex2.approx.f16x2 %0, %1;" : "=r"(r) : "r"(x)); return r;
}
__device__ __forceinline__ uint32_t smaddr(const void* p) {
    return (uint32_t)__cvta_generic_to_shared(p);
}
__device__ __forceinline__ void ldsm4(uint32_t* r, uint32_t addr) {
    asm volatile("ldmatrix.sync.aligned.m8n8.x4.shared.b16 {%0,%1,%2,%3}, [%4];"
        : "=r"(r[0]), "=r"(r[1]), "=r"(r[2]), "=r"(r[3]) : "r"(addr));
}
__device__ __forceinline__ void ldsm4t(uint32_t* r, uint32_t addr) {
    asm volatile("ldmatrix.sync.aligned.m8n8.x4.trans.shared.b16 {%0,%1,%2,%3}, [%4];"
        : "=r"(r[0]), "=r"(r[1]), "=r"(r[2]), "=r"(r[3]) : "r"(addr));
}
__device__ __forceinline__ void mma16(float* c, const uint32_t* a,
                                      uint32_t b0, uint32_t b1) {
    asm volatile(
        "mma.sync.aligned.m16n8k16.row.col.f32.f16.f16.f32 "
        "{%0,%1,%2,%3},{%4,%5,%6,%7},{%8,%9},{%0,%1,%2,%3};"
        : "+f"(c[0]), "+f"(c[1]), "+f"(c[2]), "+f"(c[3])
        : "r"(a[0]), "r"(a[1]), "r"(a[2]), "r"(a[3]), "r"(b0), "r"(b1));
}

#define SAH 136   // fp16 A stride
#define SBH 136   // fp16 B stride
#define SEF 136   // fp32 epilogue stride (out_kernel)

// ---------------- Kernel 0: one-time fp32 -> fp16 weight conversion -------
__global__ __launch_bounds__(256) void cvt_kernel(
    const float* __restrict__ wq, const float* __restrict__ wk,
    const float* __restrict__ wv, const float* __restrict__ wg,
    const float* __restrict__ wo)
{
    int idx = blockIdx.x * 256 + threadIdx.x;      // 0..4095 float4 units
    const float* srcs[5] = {wq, wk, wv, wg, wo};
    __half* dsts[5] = {g_wh[0], g_wh[1], g_wh[2], g_wh[3], g_woh};
    #pragma unroll
    for (int m = 0; m < 5; m++) {
        float4 v = ((const float4*)srcs[m])[idx];
        ((uint2*)dsts[m])[idx] =
            make_uint2(pack_h2(v.x, v.y), pack_h2(v.z, v.w));
    }
}

// ---------------- Kernel 1: fused LN + tri + q/k/v/g projection -----------
// 128-row tiles (grid halved): LN in two 64-row passes, 8 warps (2x4),
// warp tile 64x32 (mt=4 m16 tiles).
__global__ __launch_bounds__(256, 2) void proj_kernel(
    const float* __restrict__ x,
    const float* __restrict__ ln_g, const float* __restrict__ ln_b,
    const float* __restrict__ w_tri, const float* __restrict__ bg)
{
    extern __shared__ __half shh[];
    __half* As16 = shh;                  // [128][SAH]
    __half* Bs16 = As16 + 128 * SAH;     // [128][SBH]
    __half* Es   = Bs16 + 128 * SBH;     // [128][SBH] epilogue staging

    int m0 = blockIdx.x * 128;
    int tid = threadIdx.x, wid = tid >> 5, lane = tid & 31;
    int warpM = (wid >> 2) * 64, warpN = (wid & 3) * 32;
    int q4 = lane & 3, r8 = lane >> 2;

    // ---- LayerNorm + tri: 2 passes of 64 rows (4 threads x 32ch / row) ----
    #pragma unroll 1
    for (int pass = 0; pass < 2; pass++) {
        int row = (tid >> 2) + pass * 64, qq = tid & 3;
        const float4* xp = (const float4*)(x + ((size_t)(m0 + row)) * 128 + qq * 32);
        float vals[32];
        float sum = 0.0f, ss = 0.0f;
        #pragma unroll
        for (int j4 = 0; j4 < 8; j4++) {
            float4 v = xp[j4];
            vals[4*j4+0] = v.x; vals[4*j4+1] = v.y;
            vals[4*j4+2] = v.z; vals[4*j4+3] = v.w;
            sum += v.x + v.y + v.z + v.w;
            ss  += v.x*v.x + v.y*v.y + v.z*v.z + v.w*v.w;
        }
        sum += __shfl_xor_sync(~0u, sum, 1);
        sum += __shfl_xor_sync(~0u, sum, 2);
        ss  += __shfl_xor_sync(~0u, ss, 1);
        ss  += __shfl_xor_sync(~0u, ss, 2);
        float mean = sum * (1.0f / 128.0f);
        float var  = ss * (1.0f / 128.0f) - mean * mean;
        float rstd = rsqrtf(var + LN_EPS);

        __half* rp16 = As16 + row * SAH + qq * 32;
        const float4* G4 = (const float4*)ln_g + qq * 8;
        const float4* B4 = (const float4*)ln_b + qq * 8;
        const float4* W4 = (const float4*)w_tri + qq * 32;
        float p0 = 0.0f, p1 = 0.0f, p2 = 0.0f, p3 = 0.0f;
        #pragma unroll
        for (int j4 = 0; j4 < 8; j4++) {
            float4 gg = G4[j4], bb = B4[j4];
            float xn0 = (vals[4*j4+0] - mean) * rstd * gg.x + bb.x;
            float xn1 = (vals[4*j4+1] - mean) * rstd * gg.y + bb.y;
            float xn2 = (vals[4*j4+2] - mean) * rstd * gg.z + bb.z;
            float xn3 = (vals[4*j4+3] - mean) * rstd * gg.w + bb.w;
            *(uint32_t*)&rp16[4*j4+0] = pack_h2(xn0, xn1);
            *(uint32_t*)&rp16[4*j4+2] = pack_h2(xn2, xn3);
            float4 w0 = W4[4*j4+0], w1 = W4[4*j4+1];
            float4 w2 = W4[4*j4+2], w3 = W4[4*j4+3];
            p0 += xn0*w0.x + xn1*w1.x + xn2*w2.x + xn3*w3.x;
            p1 += xn0*w0.y + xn1*w1.y + xn2*w2.y + xn3*w3.y;
            p2 += xn0*w0.z + xn1*w1.z + xn2*w2.z + xn3*w3.z;
            p3 += xn0*w0.w + xn1*w1.w + xn2*w2.w + xn3*w3.w;
        }
        #pragma unroll
        for (int o = 1; o <= 2; o <<= 1) {
            p0 += __shfl_xor_sync(~0u, p0, o);
            p1 += __shfl_xor_sync(~0u, p1, o);
            p2 += __shfl_xor_sync(~0u, p2, o);
            p3 += __shfl_xor_sync(~0u, p3, o);
        }
        float pv = (qq == 0) ? p0 : (qq == 1) ? p1 : (qq == 2) ? p2 : p3;
        g_trih[(size_t)qq * ROWS + m0 + row] = __float2half(pv * LOG2E);
    }

    int L = lane;
    uint32_t aAddr = smaddr(As16 + (warpM + (L & 7) + ((L >> 3) & 1) * 8) * SAH
                                 + (L >> 4) * 8);
    uint32_t bAddr = smaddr(Bs16 + ((L & 7) + ((L >> 3) & 1) * 8) * SBH
                                 + warpN + (L >> 4) * 8);

    // ---- 4 weight GEMMs ----
    #pragma unroll 1
    for (int y = 0; y < 4; y++) {
        __half* O = (y == 0) ? g_qh : (y == 1) ? g_kh : (y == 2) ? g_vh : g_gh;

        // stage B (prior y's Bs16 frag reads fenced by the Es-write sync)
        const uint4* Wh = (const uint4*)g_wh[y];
        #pragma unroll
        for (int it = 0; it < 8; it++) {
            int idx = tid + it * 256;
            int kk = idx >> 4, c8 = idx & 15;
            *(uint4*)&Bs16[kk * SBH + c8 * 8] = Wh[idx];
        }
        __syncthreads();    // B staged; LN writes (y=0) / prior Es reads done

        float acc[4][4][4];
        #pragma unroll
        for (int mt = 0; mt < 4; mt++)
            #pragma unroll
            for (int nt = 0; nt < 4; nt++)
                #pragma unroll
                for (int u = 0; u < 4; u++) acc[mt][nt][u] = 0.0f;

        #pragma unroll
        for (int kc = 0; kc < 8; kc++) {
            uint32_t b0[4], b1[4];
            ldsm4t(b0, bAddr + kc * 16 * SBH * 2);
            ldsm4t(b1, bAddr + kc * 16 * SBH * 2 + 32);
            #pragma unroll
            for (int mt = 0; mt < 4; mt++) {
                uint32_t a[4];
                ldsm4(a, aAddr + mt * 16 * SAH * 2 + kc * 32);
                mma16(acc[mt][0], a, b0[0], b0[1]);
                mma16(acc[mt][1], a, b0[2], b0[3]);
                mma16(acc[mt][2], a, b1[0], b1[1]);
                mma16(acc[mt][3], a, b1[2], b1[3]);
            }
        }

        // ---- epilogue: STS to Es, coalesced STG ----
        const float qscale = 0.17677669529663687f * LOG2E;
        #pragma unroll
        for (int mt = 0; mt < 4; mt++) {
            int r0 = warpM + mt * 16 + r8;
            #pragma unroll
            for (int nt = 0; nt < 4; nt++) {
                int col = warpN + nt * 8 + 2 * q4;
                float v0 = acc[mt][nt][0], v1 = acc[mt][nt][1];
                float v2 = acc[mt][nt][2], v3 = acc[mt][nt][3];
                if (y == 0) { v0 *= qscale; v1 *= qscale; v2 *= qscale; v3 *= qscale; }
                if (y == 3) {
                    float b0v = bg[col], b1v = bg[col + 1];
                    v0 = 1.0f / (1.0f + __expf(-(v0 + b0v)));
                    v1 = 1.0f / (1.0f + __expf(-(v1 + b1v)));
                    v2 = 1.0f / (1.0f + __expf(-(v2 + b0v)));
                    v3 = 1.0f / (1.0f + __expf(-(v3 + b1v)));
                }
                *(uint32_t*)&Es[r0 * SBH + col]       = pack_h2(v0, v1);
                *(uint32_t*)&Es[(r0 + 8) * SBH + col] = pack_h2(v2, v3);
            }
        }
        __syncthreads();    // Es complete (also fences this y's B ldsm)
        uint4* O4 = (uint4*)(O + (size_t)m0 * 128);
        #pragma unroll
        for (int it = 0; it < 8; it++) {
            int idx = tid + it * 256;            // 0..2047 uint4s
            int rr = idx >> 4, c8 = idx & 15;
            O4[idx] = *(uint4*)&Es[rr * SBH + c8 * 8];
        }
    }
}

// ---------------- Kernel 2: fp16 MMA flash attention ----------------------
// Softmax path in half2: pack S -> HADD2 bias -> HMIN2 clamp -> ex2.f16x2.
// Exp output doubles as the PV A-fragment. l accumulated in fp32.
#define KVS 40

__global__ __launch_bounds__(768) void attn_kernel(const float* __restrict__ mask)
{
    extern __shared__ float sh[];
    __half* Ksh = (__half*)sh;                 // [384][40]
    __half* Vsh = Ksh + 384 * KVS;             // [384][40]
    __half* mbh = Vsh + 384 * KVS;             // [384] fp16 mask bias

    int i = blockIdx.x, h = blockIdx.y;
    int tid = threadIdx.x, wid = tid >> 5, lane = tid & 31;
    int q4 = lane & 3, r8 = lane >> 2;

    const uint4* K4 = (const uint4*)(g_kh + (size_t)i * J_DIM * 128 + h * 32);
    const uint4* V4 = (const uint4*)(g_vh + (size_t)i * J_DIM * 128 + h * 32);
    #pragma unroll
    for (int it = 0; it < 2; it++) {
        int idx = tid + it * 768;
        int j = idx >> 2, c8 = idx & 3;
        *(uint4*)(Ksh + j * KVS + c8 * 8) = K4[(size_t)j * 16 + c8];
        *(uint4*)(Vsh + j * KVS + c8 * 8) = V4[(size_t)j * 16 + c8];
    }
    if (tid < 384) {
        float mbv = (LOG2E * 1.0e9f) * (mask[(size_t)i * J_DIM + tid] - 1.0f);
        mbh[tid] = __float2half(fmaxf(mbv, -60000.0f));   // fp16-safe; ex2->0
    }
    __syncthreads();

    int qbase = wid * 16;
    uint32_t qa[2][4];
    {
        const __half* Qp = g_qh + ((size_t)i * J_DIM + qbase) * 128 + h * 32;
        #pragma unroll
        for (int dc = 0; dc < 2; dc++) {
            const __half* Qk = Qp + dc * 16;
            qa[dc][0] = *(const uint32_t*)&Qk[r8 * 128 + 2 * q4];
            qa[dc][1] = *(const uint32_t*)&Qk[(r8 + 8) * 128 + 2 * q4];
            qa[dc][2] = *(const uint32_t*)&Qk[r8 * 128 + 2 * q4 + 8];
            qa[dc][3] = *(const uint32_t*)&Qk[(r8 + 8) * 128 + 2 * q4 + 8];
        }
    }

    float oacc[4][4];
    #pragma unroll
    for (int dn = 0; dn < 4; dn++)
        #pragma unroll
        for (int u = 0; u < 4; u++) oacc[dn][u] = 0.0f;
    float lrow0 = 0.0f, lrow1 = 0.0f;

    const __half* triW = g_trih + (size_t)h * ROWS;
    const __half2 clamp15 = __floats2half2_rn(15.0f, 15.0f);
    int L = lane;
    uint32_t kAddr = smaddr(Ksh + (((L >> 4) & 1) * 8 + (L & 7)) * KVS
                                + ((L >> 3) & 1) * 8);
    uint32_t vAddr = smaddr(Vsh + ((L & 7) + ((L >> 3) & 1) * 8) * KVS
                                + (L >> 4) * 8);

    #pragma unroll 1
    for (int kb = 0; kb < 12; kb++) {
        int kbase = kb * 32;
        uint32_t kbB = (uint32_t)kbase * (KVS * 2);

        // ---- S = Q K^T ----
        float sacc[4][4];
        #pragma unroll
        for (int nt = 0; nt < 4; nt++)
            #pragma unroll
            for (int u = 0; u < 4; u++) sacc[nt][u] = 0.0f;

        #pragma unroll
        for (int dc = 0; dc < 2; dc++) {
            uint32_t b0[4], b1[4];
            ldsm4(b0, kAddr + kbB + dc * 32);
            ldsm4(b1, kAddr + kbB + 16 * KVS * 2 + dc * 32);
            mma16(sacc[0], qa[dc], b0[0], b0[1]);
            mma16(sacc[1], qa[dc], b0[2], b0[3]);
            mma16(sacc[2], qa[dc], b1[0], b1[1]);
            mma16(sacc[3], qa[dc], b1[2], b1[3]);
        }

        // ---- bias + exp in half2 ----
        uint32_t p2lo[4], p2hi[4];
        {
            int qrow = qbase + r8;
            const __half* t0p = triW + (size_t)qrow * J_DIM + kbase + 2 * q4;
            const __half* t1p = t0p + 8 * J_DIM;
            #pragma unroll
            for (int nt = 0; nt < 4; nt++) {
                __half2 tA = *(const __half2*)(t0p + nt * 8);
                __half2 tB = *(const __half2*)(t1p + nt * 8);
                __half2 mv = *(const __half2*)(mbh + kbase + nt * 8 + 2 * q4);
                __half2 slo = __floats2half2_rn(sacc[nt][0], sacc[nt][1]);
                __half2 shi = __floats2half2_rn(sacc[nt][2], sacc[nt][3]);
                slo = __hmin2(__hadd2(slo, __hadd2(tA, mv)), clamp15);
                shi = __hmin2(__hadd2(shi, __hadd2(tB, mv)), clamp15);
                uint32_t plo = ex2h2(*(uint32_t*)&slo);
                uint32_t phi = ex2h2(*(uint32_t*)&shi);
                p2lo[nt] = plo; p2hi[nt] = phi;
                float2 flo = __half22float2(*(__half2*)&plo);
                float2 fhi = __half22float2(*(__half2*)&phi);
                lrow0 += flo.x + flo.y;
                lrow1 += fhi.x + fhi.y;
            }
        }

        // ---- O += P V (exp output IS the A-fragment) ----
        #pragma unroll
        for (int kc = 0; kc < 2; kc++) {
            uint32_t pa[4];
            pa[0] = p2lo[2*kc];   pa[1] = p2hi[2*kc];
            pa[2] = p2lo[2*kc+1]; pa[3] = p2hi[2*kc+1];

            uint32_t vb0[4], vb1[4];
            uint32_t vOff = kbB + (uint32_t)kc * 16 * KVS * 2;
            ldsm4t(vb0, vAddr + vOff);
            ldsm4t(vb1, vAddr + vOff + 32);
            mma16(oacc[0], pa, vb0[0], vb0[1]);
            mma16(oacc[1], pa, vb0[2], vb0[3]);
            mma16(oacc[2], pa, vb1[0], vb1[1]);
            mma16(oacc[3], pa, vb1[2], vb1[3]);
        }
    }

    lrow0 += __shfl_xor_sync(~0u, lrow0, 1);
    lrow0 += __shfl_xor_sync(~0u, lrow0, 2);
    lrow1 += __shfl_xor_sync(~0u, lrow1, 1);
    lrow1 += __shfl_xor_sync(~0u, lrow1, 2);

    {
        float inv0 = 1.0f / fmaxf(lrow0, 1e-30f);
        float inv1 = 1.0f / fmaxf(lrow1, 1e-30f);
        size_t row0 = ((size_t)i * J_DIM + qbase + r8) * 128 + h * 32;
        size_t row1 = row0 + (size_t)8 * 128;
        #pragma unroll
        for (int dn = 0; dn < 4; dn++) {
            int c = dn * 8 + 2 * q4;
            float2 gv0 = __half22float2(*(const __half2*)&g_gh[row0 + c]);
            float2 gv1 = __half22float2(*(const __half2*)&g_gh[row1 + c]);
            *(uint32_t*)&g_oh[row0 + c] =
                pack_h2(oacc[dn][0] * inv0 * gv0.x, oacc[dn][1] * inv0 * gv0.y);
            *(uint32_t*)&g_oh[row1 + c] =
                pack_h2(oacc[dn][2] * inv1 * gv1.x, oacc[dn][3] * inv1 * gv1.y);
        }
    }
}

// ---------------- Kernel 3: output projection (fp16 MMA) ------------------
__global__ __launch_bounds__(256, 3) void out_kernel(
    const float* __restrict__ bo, float* __restrict__ out)
{
    extern __shared__ __half shh[];
    __half* As16 = shh;                  // [64][SAH]
    __half* Bs16 = As16 + 64 * SAH;      // [128][SBH]; reused as fp32 epilogue

    int m0 = blockIdx.x * 64;
    int tid = threadIdx.x, wid = tid >> 5, lane = tid & 31;
    int warpM = (wid >> 2) * 32, warpN = (wid & 3) * 32;
    int q4 = lane & 3, r8 = lane >> 2;

    const uint4* A4 = (const uint4*)(g_oh + (size_t)m0 * 128);
    #pragma unroll
    for (int it = 0; it < 4; it++) {
        int idx = tid + it * 256;
        int rr = idx >> 4, c8 = idx & 15;
        *(uint4*)(As16 + rr * SAH + c8 * 8) = A4[idx];
    }
    const uint4* Wh = (const uint4*)g_woh;
    #pragma unroll
    for (int it = 0; it < 8; it++) {
        int idx = tid + it * 256;
        int kk = idx >> 4, c8 = idx & 15;
        *(uint4*)&Bs16[kk * SBH + c8 * 8] = Wh[idx];
    }
    __syncthreads();

    int L = lane;
    uint32_t aAddr = smaddr(As16 + (warpM + (L & 7) + ((L >> 3) & 1) * 8) * SAH
                                 + (L >> 4) * 8);
    uint32_t bAddr = smaddr(Bs16 + ((L & 7) + ((L >> 3) & 1) * 8) * SBH
                                 + warpN + (L >> 4) * 8);

    float acc[2][4][4];
    #pragma unroll
    for (int mt = 0; mt < 2; mt++)
        #pragma unroll
        for (int nt = 0; nt < 4; nt++)
            #pragma unroll
            for (int u = 0; u < 4; u++) acc[mt][nt][u] = 0.0f;

    #pragma unroll
    for (int kc = 0; kc < 8; kc++) {
        uint32_t a0[4], a1[4], b0[4], b1[4];
        ldsm4 (a0, aAddr + kc * 32);
        ldsm4 (a1, aAddr + kc * 32 + 16 * SAH * 2);
        ldsm4t(b0, bAddr + kc * 16 * SBH * 2);
        ldsm4t(b1, bAddr + kc * 16 * SBH * 2 + 32);
        mma16(acc[0][0], a0, b0[0], b0[1]);
        mma16(acc[0][1], a0, b0[2], b0[3]);
        mma16(acc[0][2], a0, b1[0], b1[1]);
        mma16(acc[0][3], a0, b1[2], b1[3]);
        mma16(acc[1][0], a1, b0[0], b0[1]);
        mma16(acc[1][1], a1, b0[2], b0[3]);
        mma16(acc[1][2], a1, b1[0], b1[1]);
        mma16(acc[1][3], a1, b1[2], b1[3]);
    }

    __syncthreads();
    float* Es32 = (float*)Bs16;          // [64][SEF] fp32
    #pragma unroll
    for (int mt = 0; mt < 2; mt++) {
        int r0 = warpM + mt * 16 + r8;
        #pragma unroll
        for (int nt = 0; nt < 4; nt++) {
            int col = warpN + nt * 8 + 2 * q4;
            float b0v = bo[col], b1v = bo[col + 1];
            *(float2*)&Es32[r0 * SEF + col] =
                make_float2(acc[mt][nt][0] + b0v, acc[mt][nt][1] + b1v);
            *(float2*)&Es32[(r0 + 8) * SEF + col] =
                make_float2(acc[mt][nt][2] + b0v, acc[mt][nt][3] + b1v);
        }
    }
    __syncthreads();
    float4* O4 = (float4*)(out + (size_t)m0 * 128);
    #pragma unroll
    for (int it = 0; it < 8; it++) {
        int idx = tid + it * 256;
        int rr = idx >> 5, c4 = idx & 31;
        O4[idx] = *(float4*)&Es32[rr * SEF + c4 * 4];
    }
}

// ---------------- launch ---------------------------------------------------
extern "C" void kernel_launch(void* const* d_in, const int* in_sizes, int n_in,
                              void* d_out, int out_size)
{
    const float* x     = (const float*)d_in[0];
    const float* mask  = (const float*)d_in[1];
    const float* ln_g  = (const float*)d_in[2];
    const float* ln_b  = (const float*)d_in[3];
    const float* w_tri = (const float*)d_in[4];
    const float* wq    = (const float*)d_in[5];
    const float* wk    = (const float*)d_in[6];
    const float* wv    = (const float*)d_in[7];
    const float* wg    = (const float*)d_in[8];
    const float* bg    = (const float*)d_in[9];
    const float* wo    = (const float*)d_in[10];
    const float* bo    = (const float*)d_in[11];
    float* out = (float*)d_out;

    const int SMEM_PROJ = (128 * SAH + 128 * SBH + 128 * SBH) * 2;  // 104448
    const int SMEM_OUT  = 64 * SAH * 2 + 128 * SBH * 2;             // 52224
    const int SMEM_ATTN = 2 * 384 * KVS * 2 + 384 * 2;              // 62208
    cudaFuncSetAttribute(proj_kernel,
                         cudaFuncAttributeMaxDynamicSharedMemorySize, SMEM_PROJ);
    cudaFuncSetAttribute(out_kernel,
                         cudaFuncAttributeMaxDynamicSharedMemorySize, SMEM_OUT);
    cudaFuncSetAttribute(attn_kernel,
                         cudaFuncAttributeMaxDynamicSharedMemorySize, SMEM_ATTN);

    cvt_kernel<<<16, 256>>>(wq, wk, wv, wg, wo);
    proj_kernel<<<ROWS / 128, 256, SMEM_PROJ>>>(x, ln_g, ln_b, w_tri, bg);
    attn_kernel<<<dim3(I_DIM, H_DIM), 768, SMEM_ATTN>>>(mask);
    out_kernel<<<ROWS / 64, 256, SMEM_OUT>>>(bo, out);
}

// round 17
// speedup vs baseline: 1.0428x; 1.0148x over previous
#include <cuda_runtime.h>
#include <cuda_fp16.h>
#include <math.h>
#include <stdint.h>

#define I_DIM 384
#define J_DIM 384
#define C_DIM 128
#define H_DIM 4
#define ROWS (I_DIM * J_DIM)          // 147456
#define LN_EPS 1e-5f
#define LOG2E 1.4426950408889634f

// ---------------- scratch -------------------------------------------------
__device__ __half g_trih[H_DIM * ROWS];  // [h][q*384+k], pre-scaled by LOG2E
__device__ __half g_qh[ROWS * C_DIM];    // pre-scaled by (1/sqrt(32))*LOG2E
__device__ __half g_kh[ROWS * C_DIM];
__device__ __half g_vh[ROWS * C_DIM];
__device__ __half g_gh[ROWS * C_DIM];
__device__ __half g_oh[ROWS * C_DIM];
__device__ __half g_wh[4][C_DIM * C_DIM];   // wq wk wv wg (fp16)
__device__ __half g_woh[C_DIM * C_DIM];     // wo (fp16)

// ---------------- helpers -------------------------------------------------
__device__ __forceinline__ uint32_t pack_h2(float lo, float hi) {
    __half2 h = __float22half2_rn(make_float2(lo, hi));
    return *reinterpret_cast<uint32_t*>(&h);
}
__device__ __forceinline__ uint32_t ex2h2(uint32_t x) {
    uint32_t r; asm("ex2.approx.f16x2 %0, %1;" : "=r"(r) : "r"(x)); return r;
}
__device__ __forceinline__ uint32_t smaddr(const void* p) {
    return (uint32_t)__cvta_generic_to_shared(p);
}
__device__ __forceinline__ void ldsm4(uint32_t* r, uint32_t addr) {
    asm volatile("ldmatrix.sync.aligned.m8n8.x4.shared.b16 {%0,%1,%2,%3}, [%4];"
        : "=r"(r[0]), "=r"(r[1]), "=r"(r[2]), "=r"(r[3]) : "r"(addr));
}
__device__ __forceinline__ void ldsm4t(uint32_t* r, uint32_t addr) {
    asm volatile("ldmatrix.sync.aligned.m8n8.x4.trans.shared.b16 {%0,%1,%2,%3}, [%4];"
        : "=r"(r[0]), "=r"(r[1]), "=r"(r[2]), "=r"(r[3]) : "r"(addr));
}
__device__ __forceinline__ void mma16(float* c, const uint32_t* a,
                                      uint32_t b0, uint32_t b1) {
    asm volatile(
        "mma.sync.aligned.m16n8k16.row.col.f32.f16.f16.f32 "
        "{%0,%1,%2,%3},{%4,%5,%6,%7},{%8,%9},{%0,%1,%2,%3};"
        : "+f"(c[0]), "+f"(c[1]), "+f"(c[2]), "+f"(c[3])
        : "r"(a[0]), "r"(a[1]), "r"(a[2]), "r"(a[3]), "r"(b0), "r"(b1));
}
__device__ __forceinline__ void cpasync16(uint32_t saddr, const void* g) {
    asm volatile("cp.async.cg.shared.global [%0], [%1], 16;"
                 :: "r"(saddr), "l"(g) : "memory");
}
__device__ __forceinline__ void cp_commit() {
    asm volatile("cp.async.commit_group;" ::: "memory");
}
__device__ __forceinline__ void cp_wait_all() {
    asm volatile("cp.async.wait_group 0;" ::: "memory");
}

#define SAH 136   // fp16 A stride
#define SBH 136   // fp16 B stride
#define SEF 136   // fp32 epilogue stride (out_kernel)

// ---------------- Kernel 0: one-time fp32 -> fp16 weight conversion -------
__global__ __launch_bounds__(256) void cvt_kernel(
    const float* __restrict__ wq, const float* __restrict__ wk,
    const float* __restrict__ wv, const float* __restrict__ wg,
    const float* __restrict__ wo)
{
    int idx = blockIdx.x * 256 + threadIdx.x;      // 0..4095 float4 units
    const float* srcs[5] = {wq, wk, wv, wg, wo};
    __half* dsts[5] = {g_wh[0], g_wh[1], g_wh[2], g_wh[3], g_woh};
    #pragma unroll
    for (int m = 0; m < 5; m++) {
        float4 v = ((const float4*)srcs[m])[idx];
        ((uint2*)dsts[m])[idx] =
            make_uint2(pack_h2(v.x, v.y), pack_h2(v.z, v.w));
    }
}

// ---------------- Kernel 1: fused LN + tri + q/k/v/g projection -----------
// 128-row tiles: LN in two 64-row passes, 8 warps (2x4), warp tile 64x32.
__global__ __launch_bounds__(256, 2) void proj_kernel(
    const float* __restrict__ x,
    const float* __restrict__ ln_g, const float* __restrict__ ln_b,
    const float* __restrict__ w_tri, const float* __restrict__ bg)
{
    extern __shared__ __half shh[];
    __half* As16 = shh;                  // [128][SAH]
    __half* Bs16 = As16 + 128 * SAH;     // [128][SBH]
    __half* Es   = Bs16 + 128 * SBH;     // [128][SBH] epilogue staging

    int m0 = blockIdx.x * 128;
    int tid = threadIdx.x, wid = tid >> 5, lane = tid & 31;
    int warpM = (wid >> 2) * 64, warpN = (wid & 3) * 32;
    int q4 = lane & 3, r8 = lane >> 2;

    // ---- LayerNorm + tri: 2 passes of 64 rows (4 threads x 32ch / row) ----
    #pragma unroll 1
    for (int pass = 0; pass < 2; pass++) {
        int row = (tid >> 2) + pass * 64, qq = tid & 3;
        const float4* xp = (const float4*)(x + ((size_t)(m0 + row)) * 128 + qq * 32);
        float vals[32];
        float sum = 0.0f, ss = 0.0f;
        #pragma unroll
        for (int j4 = 0; j4 < 8; j4++) {
            float4 v = xp[j4];
            vals[4*j4+0] = v.x; vals[4*j4+1] = v.y;
            vals[4*j4+2] = v.z; vals[4*j4+3] = v.w;
            sum += v.x + v.y + v.z + v.w;
            ss  += v.x*v.x + v.y*v.y + v.z*v.z + v.w*v.w;
        }
        sum += __shfl_xor_sync(~0u, sum, 1);
        sum += __shfl_xor_sync(~0u, sum, 2);
        ss  += __shfl_xor_sync(~0u, ss, 1);
        ss  += __shfl_xor_sync(~0u, ss, 2);
        float mean = sum * (1.0f / 128.0f);
        float var  = ss * (1.0f / 128.0f) - mean * mean;
        float rstd = rsqrtf(var + LN_EPS);

        __half* rp16 = As16 + row * SAH + qq * 32;
        const float4* G4 = (const float4*)ln_g + qq * 8;
        const float4* B4 = (const float4*)ln_b + qq * 8;
        const float4* W4 = (const float4*)w_tri + qq * 32;
        float p0 = 0.0f, p1 = 0.0f, p2 = 0.0f, p3 = 0.0f;
        #pragma unroll
        for (int j4 = 0; j4 < 8; j4++) {
            float4 gg = G4[j4], bb = B4[j4];
            float xn0 = (vals[4*j4+0] - mean) * rstd * gg.x + bb.x;
            float xn1 = (vals[4*j4+1] - mean) * rstd * gg.y + bb.y;
            float xn2 = (vals[4*j4+2] - mean) * rstd * gg.z + bb.z;
            float xn3 = (vals[4*j4+3] - mean) * rstd * gg.w + bb.w;
            *(uint32_t*)&rp16[4*j4+0] = pack_h2(xn0, xn1);
            *(uint32_t*)&rp16[4*j4+2] = pack_h2(xn2, xn3);
            float4 w0 = W4[4*j4+0], w1 = W4[4*j4+1];
            float4 w2 = W4[4*j4+2], w3 = W4[4*j4+3];
            p0 += xn0*w0.x + xn1*w1.x + xn2*w2.x + xn3*w3.x;
            p1 += xn0*w0.y + xn1*w1.y + xn2*w2.y + xn3*w3.y;
            p2 += xn0*w0.z + xn1*w1.z + xn2*w2.z + xn3*w3.z;
            p3 += xn0*w0.w + xn1*w1.w + xn2*w2.w + xn3*w3.w;
        }
        #pragma unroll
        for (int o = 1; o <= 2; o <<= 1) {
            p0 += __shfl_xor_sync(~0u, p0, o);
            p1 += __shfl_xor_sync(~0u, p1, o);
            p2 += __shfl_xor_sync(~0u, p2, o);
            p3 += __shfl_xor_sync(~0u, p3, o);
        }
        float pv = (qq == 0) ? p0 : (qq == 1) ? p1 : (qq == 2) ? p2 : p3;
        g_trih[(size_t)qq * ROWS + m0 + row] = __float2half(pv * LOG2E);
    }

    int L = lane;
    uint32_t aAddr = smaddr(As16 + (warpM + (L & 7) + ((L >> 3) & 1) * 8) * SAH
                                 + (L >> 4) * 8);
    uint32_t bAddr = smaddr(Bs16 + ((L & 7) + ((L >> 3) & 1) * 8) * SBH
                                 + warpN + (L >> 4) * 8);

    // ---- 4 weight GEMMs ----
    #pragma unroll 1
    for (int y = 0; y < 4; y++) {
        __half* O = (y == 0) ? g_qh : (y == 1) ? g_kh : (y == 2) ? g_vh : g_gh;

        const uint4* Wh = (const uint4*)g_wh[y];
        #pragma unroll
        for (int it = 0; it < 8; it++) {
            int idx = tid + it * 256;
            int kk = idx >> 4, c8 = idx & 15;
            *(uint4*)&Bs16[kk * SBH + c8 * 8] = Wh[idx];
        }
        __syncthreads();    // B staged; LN writes (y=0) / prior Es reads done

        float acc[4][4][4];
        #pragma unroll
        for (int mt = 0; mt < 4; mt++)
            #pragma unroll
            for (int nt = 0; nt < 4; nt++)
                #pragma unroll
                for (int u = 0; u < 4; u++) acc[mt][nt][u] = 0.0f;

        #pragma unroll
        for (int kc = 0; kc < 8; kc++) {
            uint32_t b0[4], b1[4];
            ldsm4t(b0, bAddr + kc * 16 * SBH * 2);
            ldsm4t(b1, bAddr + kc * 16 * SBH * 2 + 32);
            #pragma unroll
            for (int mt = 0; mt < 4; mt++) {
                uint32_t a[4];
                ldsm4(a, aAddr + mt * 16 * SAH * 2 + kc * 32);
                mma16(acc[mt][0], a, b0[0], b0[1]);
                mma16(acc[mt][1], a, b0[2], b0[3]);
                mma16(acc[mt][2], a, b1[0], b1[1]);
                mma16(acc[mt][3], a, b1[2], b1[3]);
            }
        }

        // ---- epilogue: STS to Es, coalesced STG ----
        const float qscale = 0.17677669529663687f * LOG2E;
        #pragma unroll
        for (int mt = 0; mt < 4; mt++) {
            int r0 = warpM + mt * 16 + r8;
            #pragma unroll
            for (int nt = 0; nt < 4; nt++) {
                int col = warpN + nt * 8 + 2 * q4;
                float v0 = acc[mt][nt][0], v1 = acc[mt][nt][1];
                float v2 = acc[mt][nt][2], v3 = acc[mt][nt][3];
                if (y == 0) { v0 *= qscale; v1 *= qscale; v2 *= qscale; v3 *= qscale; }
                if (y == 3) {
                    float b0v = bg[col], b1v = bg[col + 1];
                    v0 = 1.0f / (1.0f + __expf(-(v0 + b0v)));
                    v1 = 1.0f / (1.0f + __expf(-(v1 + b1v)));
                    v2 = 1.0f / (1.0f + __expf(-(v2 + b0v)));
                    v3 = 1.0f / (1.0f + __expf(-(v3 + b1v)));
                }
                *(uint32_t*)&Es[r0 * SBH + col]       = pack_h2(v0, v1);
                *(uint32_t*)&Es[(r0 + 8) * SBH + col] = pack_h2(v2, v3);
            }
        }
        __syncthreads();    // Es complete (also fences this y's B ldsm)
        uint4* O4 = (uint4*)(O + (size_t)m0 * 128);
        #pragma unroll
        for (int it = 0; it < 8; it++) {
            int idx = tid + it * 256;            // 0..2047 uint4s
            int rr = idx >> 4, c8 = idx & 15;
            O4[idx] = *(uint4*)&Es[rr * SBH + c8 * 8];
        }
    }
}

// ---------------- Kernel 2: fp16 MMA flash attention ----------------------
// Single-group cp.async staging (R14 indexing) overlapped with mbh + Q loads.
// Softmax in half2 (ex2.f16x2); exp output IS the PV A-fragment.
// l computed by an extra MMA against a constant all-ones B fragment — no
// per-iter ALU accumulation, no end-of-kernel shuffles.
#define KVS 40
#define ONES_H2 0x3C003C00u   // half2(1.0, 1.0)

__global__ __launch_bounds__(768) void attn_kernel(const float* __restrict__ mask)
{
    extern __shared__ float sh[];
    __half* Ksh = (__half*)sh;                 // [384][40]
    __half* Vsh = Ksh + 384 * KVS;             // [384][40]
    __half* mbh = Vsh + 384 * KVS;             // [384] fp16 mask bias

    int i = blockIdx.x, h = blockIdx.y;
    int tid = threadIdx.x, wid = tid >> 5, lane = tid & 31;
    int q4 = lane & 3, r8 = lane >> 2;

    const uint4* K4 = (const uint4*)(g_kh + (size_t)i * J_DIM * 128 + h * 32);
    const uint4* V4 = (const uint4*)(g_vh + (size_t)i * J_DIM * 128 + h * 32);
    // Exactly R14's staging indexing, via cp.async (one group, wait-all).
    #pragma unroll
    for (int it = 0; it < 2; it++) {
        int idx = tid + it * 768;            // 0..1535
        int j = idx >> 2, c8 = idx & 3;
        cpasync16(smaddr(Ksh + j * KVS + c8 * 8), K4 + (size_t)j * 16 + c8);
        cpasync16(smaddr(Vsh + j * KVS + c8 * 8), V4 + (size_t)j * 16 + c8);
    }
    cp_commit();

    // overlap with staging flight: mask bias + Q fragments
    if (tid < 384) {
        float mbv = (LOG2E * 1.0e9f) * (mask[(size_t)i * J_DIM + tid] - 1.0f);
        mbh[tid] = __float2half(fmaxf(mbv, -60000.0f));   // fp16-safe; ex2->0
    }
    int qbase = wid * 16;
    uint32_t qa[2][4];
    {
        const __half* Qp = g_qh + ((size_t)i * J_DIM + qbase) * 128 + h * 32;
        #pragma unroll
        for (int dc = 0; dc < 2; dc++) {
            const __half* Qk = Qp + dc * 16;
            qa[dc][0] = *(const uint32_t*)&Qk[r8 * 128 + 2 * q4];
            qa[dc][1] = *(const uint32_t*)&Qk[(r8 + 8) * 128 + 2 * q4];
            qa[dc][2] = *(const uint32_t*)&Qk[r8 * 128 + 2 * q4 + 8];
            qa[dc][3] = *(const uint32_t*)&Qk[(r8 + 8) * 128 + 2 * q4 + 8];
        }
    }
    cp_wait_all();
    __syncthreads();

    float oacc[4][4];
    #pragma unroll
    for (int dn = 0; dn < 4; dn++)
        #pragma unroll
        for (int u = 0; u < 4; u++) oacc[dn][u] = 0.0f;
    float oext[4] = {0.0f, 0.0f, 0.0f, 0.0f};   // l accumulator (ones-MMA)

    const __half* triW = g_trih + (size_t)h * ROWS;
    const __half2 clamp15 = __floats2half2_rn(15.0f, 15.0f);
    int L = lane;
    uint32_t kAddr = smaddr(Ksh + (((L >> 4) & 1) * 8 + (L & 7)) * KVS
                                + ((L >> 3) & 1) * 8);
    uint32_t vAddr = smaddr(Vsh + ((L & 7) + ((L >> 3) & 1) * 8) * KVS
                                + (L >> 4) * 8);

    #pragma unroll 1
    for (int kb = 0; kb < 12; kb++) {
        int kbase = kb * 32;
        uint32_t kbB = (uint32_t)kbase * (KVS * 2);

        // ---- S = Q K^T ----
        float sacc[4][4];
        #pragma unroll
        for (int nt = 0; nt < 4; nt++)
            #pragma unroll
            for (int u = 0; u < 4; u++) sacc[nt][u] = 0.0f;

        #pragma unroll
        for (int dc = 0; dc < 2; dc++) {
            uint32_t b0[4], b1[4];
            ldsm4(b0, kAddr + kbB + dc * 32);
            ldsm4(b1, kAddr + kbB + 16 * KVS * 2 + dc * 32);
            mma16(sacc[0], qa[dc], b0[0], b0[1]);
            mma16(sacc[1], qa[dc], b0[2], b0[3]);
            mma16(sacc[2], qa[dc], b1[0], b1[1]);
            mma16(sacc[3], qa[dc], b1[2], b1[3]);
        }

        // ---- bias + exp in half2 ----
        uint32_t p2lo[4], p2hi[4];
        {
            int qrow = qbase + r8;
            const __half* t0p = triW + (size_t)qrow * J_DIM + kbase + 2 * q4;
            const __half* t1p = t0p + 8 * J_DIM;
            #pragma unroll
            for (int nt = 0; nt < 4; nt++) {
                __half2 tA = *(const __half2*)(t0p + nt * 8);
                __half2 tB = *(const __half2*)(t1p + nt * 8);
                __half2 mv = *(const __half2*)(mbh + kbase + nt * 8 + 2 * q4);
                __half2 slo = __floats2half2_rn(sacc[nt][0], sacc[nt][1]);
                __half2 shi = __floats2half2_rn(sacc[nt][2], sacc[nt][3]);
                slo = __hmin2(__hadd2(slo, __hadd2(tA, mv)), clamp15);
                shi = __hmin2(__hadd2(shi, __hadd2(tB, mv)), clamp15);
                p2lo[nt] = ex2h2(*(uint32_t*)&slo);
                p2hi[nt] = ex2h2(*(uint32_t*)&shi);
            }
        }

        // ---- O += P V; l += P·1 (constant ones B-fragment) ----
        #pragma unroll
        for (int kc = 0; kc < 2; kc++) {
            uint32_t pa[4];
            pa[0] = p2lo[2*kc];   pa[1] = p2hi[2*kc];
            pa[2] = p2lo[2*kc+1]; pa[3] = p2hi[2*kc+1];

            uint32_t vb0[4], vb1[4];
            uint32_t vOff = kbB + (uint32_t)kc * 16 * KVS * 2;
            ldsm4t(vb0, vAddr + vOff);
            ldsm4t(vb1, vAddr + vOff + 32);
            mma16(oacc[0], pa, vb0[0], vb0[1]);
            mma16(oacc[1], pa, vb0[2], vb0[3]);
            mma16(oacc[2], pa, vb1[0], vb1[1]);
            mma16(oacc[3], pa, vb1[2], vb1[3]);
            mma16(oext,    pa, ONES_H2, ONES_H2);   // row sums -> l
        }
    }

    // ---- finalize: 1/l (every lane of the ones tile holds l), gate, store --
    {
        float inv0 = 1.0f / fmaxf(oext[0], 1e-30f);
        float inv1 = 1.0f / fmaxf(oext[2], 1e-30f);
        size_t row0 = ((size_t)i * J_DIM + qbase + r8) * 128 + h * 32;
        size_t row1 = row0 + (size_t)8 * 128;
        #pragma unroll
        for (int dn = 0; dn < 4; dn++) {
            int c = dn * 8 + 2 * q4;
            float2 gv0 = __half22float2(*(const __half2*)&g_gh[row0 + c]);
            float2 gv1 = __half22float2(*(const __half2*)&g_gh[row1 + c]);
            *(uint32_t*)&g_oh[row0 + c] =
                pack_h2(oacc[dn][0] * inv0 * gv0.x, oacc[dn][1] * inv0 * gv0.y);
            *(uint32_t*)&g_oh[row1 + c] =
                pack_h2(oacc[dn][2] * inv1 * gv1.x, oacc[dn][3] * inv1 * gv1.y);
        }
    }
}

// ---------------- Kernel 3: output projection (fp16 MMA) ------------------
__global__ __launch_bounds__(256, 3) void out_kernel(
    const float* __restrict__ bo, float* __restrict__ out)
{
    extern __shared__ __half shh[];
    __half* As16 = shh;                  // [64][SAH]
    __half* Bs16 = As16 + 64 * SAH;      // [128][SBH]; reused as fp32 epilogue

    int m0 = blockIdx.x * 64;
    int tid = threadIdx.x, wid = tid >> 5, lane = tid & 31;
    int warpM = (wid >> 2) * 32, warpN = (wid & 3) * 32;
    int q4 = lane & 3, r8 = lane >> 2;

    const uint4* A4 = (const uint4*)(g_oh + (size_t)m0 * 128);
    #pragma unroll
    for (int it = 0; it < 4; it++) {
        int idx = tid + it * 256;
        int rr = idx >> 4, c8 = idx & 15;
        *(uint4*)(As16 + rr * SAH + c8 * 8) = A4[idx];
    }
    const uint4* Wh = (const uint4*)g_woh;
    #pragma unroll
    for (int it = 0; it < 8; it++) {
        int idx = tid + it * 256;
        int kk = idx >> 4, c8 = idx & 15;
        *(uint4*)&Bs16[kk * SBH + c8 * 8] = Wh[idx];
    }
    __syncthreads();

    int L = lane;
    uint32_t aAddr = smaddr(As16 + (warpM + (L & 7) + ((L >> 3) & 1) * 8) * SAH
                                 + (L >> 4) * 8);
    uint32_t bAddr = smaddr(Bs16 + ((L & 7) + ((L >> 3) & 1) * 8) * SBH
                                 + warpN + (L >> 4) * 8);

    float acc[2][4][4];
    #pragma unroll
    for (int mt = 0; mt < 2; mt++)
        #pragma unroll
        for (int nt = 0; nt < 4; nt++)
            #pragma unroll
            for (int u = 0; u < 4; u++) acc[mt][nt][u] = 0.0f;

    #pragma unroll
    for (int kc = 0; kc < 8; kc++) {
        uint32_t a0[4], a1[4], b0[4], b1[4];
        ldsm4 (a0, aAddr + kc * 32);
        ldsm4 (a1, aAddr + kc * 32 + 16 * SAH * 2);
        ldsm4t(b0, bAddr + kc * 16 * SBH * 2);
        ldsm4t(b1, bAddr + kc * 16 * SBH * 2 + 32);
        mma16(acc[0][0], a0, b0[0], b0[1]);
        mma16(acc[0][1], a0, b0[2], b0[3]);
        mma16(acc[0][2], a0, b1[0], b1[1]);
        mma16(acc[0][3], a0, b1[2], b1[3]);
        mma16(acc[1][0], a1, b0[0], b0[1]);
        mma16(acc[1][1], a1, b0[2], b0[3]);
        mma16(acc[1][2], a1, b1[0], b1[1]);
        mma16(acc[1][3], a1, b1[2], b1[3]);
    }

    __syncthreads();
    float* Es32 = (float*)Bs16;          // [64][SEF] fp32
    #pragma unroll
    for (int mt = 0; mt < 2; mt++) {
        int r0 = warpM + mt * 16 + r8;
        #pragma unroll
        for (int nt = 0; nt < 4; nt++) {
            int col = warpN + nt * 8 + 2 * q4;
            float b0v = bo[col], b1v = bo[col + 1];
            *(float2*)&Es32[r0 * SEF + col] =
                make_float2(acc[mt][nt][0] + b0v, acc[mt][nt][1] + b1v);
            *(float2*)&Es32[(r0 + 8) * SEF + col] =
                make_float2(acc[mt][nt][2] + b0v, acc[mt][nt][3] + b1v);
        }
    }
    __syncthreads();
    float4* O4 = (float4*)(out + (size_t)m0 * 128);
    #pragma unroll
    for (int it = 0; it < 8; it++) {
        int idx = tid + it * 256;
        int rr = idx >> 5, c4 = idx & 31;
        O4[idx] = *(float4*)&Es32[rr * SEF + c4 * 4];
    }
}

// ---------------- launch ---------------------------------------------------
extern "C" void kernel_launch(void* const* d_in, const int* in_sizes, int n_in,
                              void* d_out, int out_size)
{
    const float* x     = (const float*)d_in[0];
    const float* mask  = (const float*)d_in[1];
    const float* ln_g  = (const float*)d_in[2];
    const float* ln_b  = (const float*)d_in[3];
    const float* w_tri = (const float*)d_in[4];
    const float* wq    = (const float*)d_in[5];
    const float* wk    = (const float*)d_in[6];
    const float* wv    = (const float*)d_in[7];
    const float* wg    = (const float*)d_in[8];
    const float* bg    = (const float*)d_in[9];
    const float* wo    = (const float*)d_in[10];
    const float* bo    = (const float*)d_in[11];
    float* out = (float*)d_out;

    const int SMEM_PROJ = (128 * SAH + 128 * SBH + 128 * SBH) * 2;  // 104448
    const int SMEM_OUT  = 64 * SAH * 2 + 128 * SBH * 2;             // 52224
    const int SMEM_ATTN = 2 * 384 * KVS * 2 + 384 * 2;              // 62208
    cudaFuncSetAttribute(proj_kernel,
                         cudaFuncAttributeMaxDynamicSharedMemorySize, SMEM_PROJ);
    cudaFuncSetAttribute(out_kernel,
                         cudaFuncAttributeMaxDynamicSharedMemorySize, SMEM_OUT);
    cudaFuncSetAttribute(attn_kernel,
                         cudaFuncAttributeMaxDynamicSharedMemorySize, SMEM_ATTN);

    cvt_kernel<<<16, 256>>>(wq, wk, wv, wg, wo);
    proj_kernel<<<ROWS / 128, 256, SMEM_PROJ>>>(x, ln_g, ln_b, w_tri, bg);
    attn_kernel<<<dim3(I_DIM, H_DIM), 768, SMEM_ATTN>>>(mask);
    out_kernel<<<ROWS / 64, 256, SMEM_OUT>>>(bo, out);
}